// round 10
// baseline (speedup 1.0000x reference)
#include <cuda_runtime.h>
#include <cuda_bf16.h>
#include <math.h>

#define NIMG 8
#define CH 512
#define HH 50
#define WW 62
#define HW 3100            // 50*62
#define NANCH 27900        // HW*9
#define NPAD 32768
#define NPRE 6000
#define NPOST 300

// d_out layout (float32):
// [0, 892800)            rpn_locs   (8, 27900, 4)
// [892800, 1339200)      rpn_scores (8, 27900, 2)
// [1339200, 1348800)     rois       (2400, 4)
// [1348800, 1351200)     roi_indices(2400)
// [1351200, 1462800)     anchor     (27900, 4)
#define OFF_SCORES 892800
#define OFF_ROIS   1339200
#define OFF_RIDX   1348800
#define OFF_ANCH   1351200

// ---------------- scratch (device globals; no allocation) ----------------
__device__ float        g_h[NIMG * HW * CH];        // conv1 output, pixel-major [n][p][c]
__device__ float        g_wt[9 * CH * CH];          // weights transposed [tap][ci][oc]
__device__ float        g_fg[NIMG * NANCH];
__device__ float        g_roi[NIMG * NANCH * 4];
__device__ float        g_anchor[NANCH * 4];
__device__ unsigned int g_key[NIMG * NPAD];
__device__ float        g_topbox[NIMG * NPRE * 4];
__device__ unsigned int g_topkey[NIMG * NPRE];
__device__ int          g_sel[NIMG * NPOST];
__device__ int          g_val[NIMG * NPOST];

__device__ __forceinline__ unsigned int packf(float f) {
    unsigned int u = __float_as_uint(f);
    return (u & 0x80000000u) ? ~u : (u | 0x80000000u);
}
#define NEGINF_KEY 0x007FFFFFu   // packf(-inf)

__device__ __forceinline__ float read_scalar(const void* p) {
    int iv = *(const int*)p;
    float fv = *(const float*)p;
    if (iv > 0 && iv < 100000) return (float)iv;
    return fv;
}

// ---------------- 0: weight transpose [oc][ci][tap] -> [tap][ci][oc] ----------------
__global__ void wtrans_kernel(const float* __restrict__ w) {
    int t = blockIdx.x * 256 + threadIdx.x;
    if (t >= CH * CH * 9) return;
    int tap = t % 9;
    int ci  = (t / 9) % CH;
    int oc  = t / (9 * CH);
    g_wt[(tap * CH + ci) * CH + oc] = w[t];
}

// ---------------- 1: 3x3 conv + bias + ReLU ----------------
// BIT-EXACT rewrite of the R9 (passing) conv:
//  - same 8-way CONTIGUOUS split over k=(ci,tap) (chunks of 64 ci), same
//    per-chunk sequential order (c0 asc, ci, tap), same pairwise tree combine.
//  - v (split id) is now a compile-time constant (unrolled) -> accumulators
//    stay in registers (R9 indexed acc[v] with runtime v -> local-mem spills).
//  - fma.rn.f32x2: two adjacent-oc outputs per instruction. Per-component
//    arithmetic is correctly-rounded fp32 FMA == fmaf, so results are
//    bit-identical; fma-pipe throughput doubles.
__global__ void __launch_bounds__(256) conv3x3_kernel(
    const float* __restrict__ x, const float* __restrict__ bias)
{
    __shared__ __align__(16) float As[8 * 9 * 64];          // [ci][tap][oc] 18 KB
    __shared__ __align__(16) unsigned long long Bp2[8 * 4 * 64]; // dup-packed input 16 KB

    int tid = threadIdx.x;
    int ty = tid >> 4;
    int tx = tid & 15;
    int y0  = blockIdx.x;
    int ocB = blockIdx.y * 64;
    int n   = blockIdx.z;

    unsigned asb = (unsigned)__cvta_generic_to_shared(As);
    unsigned bpb = (unsigned)__cvta_generic_to_shared(Bp2);

    // acc2[v][ocpair][px]: component0 = oc ty*4+2p, component1 = oc ty*4+2p+1
    unsigned long long acc2[8][2][4];
#pragma unroll
    for (int v = 0; v < 8; v++)
#pragma unroll
        for (int p = 0; p < 2; p++)
#pragma unroll
            for (int k = 0; k < 4; k++) acc2[v][p][k] = 0ull;

#pragma unroll
    for (int v = 0; v < 8; v++) {
#pragma unroll 1
        for (int cb = 0; cb < 8; cb++) {
            int c0 = v * 64 + cb * 8;
            // weights
#pragma unroll
            for (int l = 0; l < 18; l++) {
                int t2 = tid + l * 256;
                int oc  = t2 & 63;
                int rest = t2 >> 6;
                int tap = rest % 9;
                int ci  = rest / 9;
                As[ci * 576 + tap * 64 + oc] =
                    g_wt[((size_t)tap * CH + c0 + ci) * CH + ocB + oc];
            }
            // input patch, duplicated into both f32x2 lanes
#pragma unroll
            for (int l = 0; l < 8; l++) {
                int t2 = tid + l * 256;
                int c  = t2 & 63;
                int r  = (t2 >> 6) & 3;
                int ci = t2 >> 8;
                int yy = y0 + r - 1;
                int xx = c - 1;
                float vv = 0.f;
                if (yy >= 0 && yy < HH && xx >= 0 && xx < WW)
                    vv = x[(((size_t)n * CH + c0 + ci) * HH + yy) * WW + xx];
                unsigned long long pk;
                asm("mov.b64 %0, {%1, %2};" : "=l"(pk) : "f"(vv), "f"(vv));
                Bp2[ci * 256 + r * 64 + c] = pk;
            }
            __syncthreads();

#pragma unroll 1
            for (int ci = 0; ci < 8; ci++) {
                unsigned abase = asb + (unsigned)(ci * 2304 + ty * 16);
                unsigned bbase = bpb + (unsigned)(ci * 2048 + tx * 32);
#pragma unroll
                for (int tap = 0; tap < 9; tap++) {
                    const int dy = tap / 3, dx = tap % 3;
                    unsigned long long a01, a23;
                    asm("ld.shared.v2.u64 {%0, %1}, [%2];"
                        : "=l"(a01), "=l"(a23)
                        : "r"(abase + (unsigned)(tap * 256)));
                    unsigned baddr = bbase + (unsigned)(dy * 512 + dx * 8);
                    unsigned long long b0, b1, b2, b3;
                    asm("ld.shared.u64 %0, [%1];" : "=l"(b0) : "r"(baddr));
                    asm("ld.shared.u64 %0, [%1];" : "=l"(b1) : "r"(baddr + 8u));
                    asm("ld.shared.u64 %0, [%1];" : "=l"(b2) : "r"(baddr + 16u));
                    asm("ld.shared.u64 %0, [%1];" : "=l"(b3) : "r"(baddr + 24u));
                    asm("fma.rn.f32x2 %0, %1, %2, %0;" : "+l"(acc2[v][0][0]) : "l"(a01), "l"(b0));
                    asm("fma.rn.f32x2 %0, %1, %2, %0;" : "+l"(acc2[v][0][1]) : "l"(a01), "l"(b1));
                    asm("fma.rn.f32x2 %0, %1, %2, %0;" : "+l"(acc2[v][0][2]) : "l"(a01), "l"(b2));
                    asm("fma.rn.f32x2 %0, %1, %2, %0;" : "+l"(acc2[v][0][3]) : "l"(a01), "l"(b3));
                    asm("fma.rn.f32x2 %0, %1, %2, %0;" : "+l"(acc2[v][1][0]) : "l"(a23), "l"(b0));
                    asm("fma.rn.f32x2 %0, %1, %2, %0;" : "+l"(acc2[v][1][1]) : "l"(a23), "l"(b1));
                    asm("fma.rn.f32x2 %0, %1, %2, %0;" : "+l"(acc2[v][1][2]) : "l"(a23), "l"(b2));
                    asm("fma.rn.f32x2 %0, %1, %2, %0;" : "+l"(acc2[v][1][3]) : "l"(a23), "l"(b3));
                }
            }
            __syncthreads();
        }
    }

#pragma unroll
    for (int j = 0; j < 4; j++) {
        int px = tx * 4 + j;
        if (px >= WW) continue;
        int p = y0 * WW + px;
#pragma unroll
        for (int i = 0; i < 4; i++) {
            int oc = ocB + ty * 4 + i;
            float av[8];
#pragma unroll
            for (int v = 0; v < 8; v++) {
                float lo, hi;
                asm("mov.b64 {%0, %1}, %2;"
                    : "=f"(lo), "=f"(hi) : "l"(acc2[v][i >> 1][j]));
                av[v] = (i & 1) ? hi : lo;
            }
            // pairwise tree combine, identical to the passing R9 kernel
            float s01 = __fadd_rn(av[0], av[1]);
            float s23 = __fadd_rn(av[2], av[3]);
            float s45 = __fadd_rn(av[4], av[5]);
            float s67 = __fadd_rn(av[6], av[7]);
            float r = __fadd_rn(__fadd_rn(s01, s23), __fadd_rn(s45, s67));
            float vv = r + bias[oc];
            g_h[((size_t)n * HW + p) * CH + oc] = fmaxf(vv, 0.f);
        }
    }
}

// ---------------- 2: head 1x1 convs (8-way contiguous split, tree combine) ----------------
__global__ void heads_kernel(const float* __restrict__ loc_w, const float* __restrict__ loc_b,
                             const float* __restrict__ sc_w,  const float* __restrict__ sc_b,
                             float* __restrict__ out)
{
    __shared__ float hs[8 * CH];
    int g = blockIdx.x;
    int n = g / 388;
    int p0 = (g % 388) * 8;
    for (int l = threadIdx.x; l < 8 * CH; l += 256) {
        int pp = l >> 9, c = l & 511;
        int p = p0 + pp;
        hs[l] = (p < HW) ? g_h[((size_t)n * HW + p) * CH + c] : 0.f;
    }
    __syncthreads();
    for (int job = threadIdx.x; job < 432; job += 256) {
        int pp = job / 54, o = job % 54;
        int p = p0 + pp;
        if (p >= HW) continue;
        const float* wrow;
        float b;
        if (o < 36) { wrow = loc_w + o * CH; b = loc_b[o]; }
        else        { wrow = sc_w + (o - 36) * CH; b = sc_b[o - 36]; }
        const float* h = &hs[pp * CH];
        float sv[8];
#pragma unroll
        for (int v = 0; v < 8; v++) {
            float s = 0.f;
            int base = v * 64;
#pragma unroll 8
            for (int c = 0; c < 64; c++)
                s = fmaf(h[base + c], wrow[base + c], s);
            sv[v] = s;
        }
        float s01 = __fadd_rn(sv[0], sv[1]);
        float s23 = __fadd_rn(sv[2], sv[3]);
        float s45 = __fadd_rn(sv[4], sv[5]);
        float s67 = __fadd_rn(sv[6], sv[7]);
        float s = __fadd_rn(__fadd_rn(s01, s23), __fadd_rn(s45, s67)) + b;
        if (o < 36) out[(size_t)n * 111600 + p * 36 + o] = s;
        else        out[OFF_SCORES + (size_t)n * 55800 + p * 18 + (o - 36)] = s;
    }
}

// ---------------- 2b: softmax fg scores ----------------
__global__ void fg_kernel(const float* __restrict__ out) {
    int t = blockIdx.x * 256 + threadIdx.x;
    if (t >= NIMG * NANCH) return;
    int n = t / NANCH, i = t % NANCH;
    int p = i / 9, a = i % 9;
    const float* s = out + OFF_SCORES + (size_t)n * 55800 + p * 18 + a * 2;
    float s0 = s[0], s1 = s[1];
    float m = fmaxf(s0, s1);
    float e0 = expf(s0 - m);
    float e1 = expf(s1 - m);
    g_fg[t] = e1 / (e0 + e1);
}

// ---------------- 3: anchors ----------------
__global__ void anchor_kernel(float* __restrict__ out) {
    int t = blockIdx.x * 256 + threadIdx.x;
    if (t >= NANCH) return;
    int p = t / 9, a = t % 9;
    int y = p / WW, x = p - y * WW;
    int ridx = a / 3, sidx = a % 3;
    double r = (ridx == 0) ? 0.5 : ((ridx == 1) ? 1.0 : 2.0);
    double s = (sidx == 0) ? 8.0 : ((sidx == 1) ? 16.0 : 32.0);
    double hb = 16.0 * s * sqrt(r);
    double wb = 16.0 * s * sqrt(1.0 / r);
    float a0 = (float)(8.0 - hb / 2.0);
    float a1 = (float)(8.0 - wb / 2.0);
    float a2 = (float)(8.0 + hb / 2.0);
    float a3 = (float)(8.0 + wb / 2.0);
    float sy = (float)y * 16.0f, sx = (float)x * 16.0f;
    float v0 = a0 + sy, v1 = a1 + sx;
    float v2 = a2 + sy, v3 = a3 + sx;
    g_anchor[t * 4 + 0] = v0; g_anchor[t * 4 + 1] = v1;
    g_anchor[t * 4 + 2] = v2; g_anchor[t * 4 + 3] = v3;
    out[OFF_ANCH + t * 4 + 0] = v0; out[OFF_ANCH + t * 4 + 1] = v1;
    out[OFF_ANCH + t * 4 + 2] = v2; out[OFF_ANCH + t * 4 + 3] = v3;
}

// ---------------- 4: decode boxes + clip + filter + pack sort keys ----------------
__global__ void decode_kernel(const float* __restrict__ out, const void* ph, const void* pw) {
    int t = blockIdx.x * 256 + threadIdx.x;
    if (t >= NIMG * NPAD) return;
    int n = t >> 15, i = t & (NPAD - 1);
    if (i >= NANCH) { g_key[t] = 0u; return; }
    float fh = read_scalar(ph), fw = read_scalar(pw);
    const float* A = &g_anchor[i * 4];
    float ah = A[2] - A[0];
    float aw = A[3] - A[1];
    float cy = A[0] + 0.5f * ah;
    float cx = A[1] + 0.5f * aw;
    const float* L = out + (size_t)n * 111600 + (size_t)i * 4;
    float dy = L[0], dx = L[1], dh = L[2], dw = L[3];
    float ncy = dy * ah + cy;
    float ncx = dx * aw + cx;
    float nh = expf(dh) * ah;
    float nw = expf(dw) * aw;
    float b0 = ncy - 0.5f * nh;
    float b1 = ncx - 0.5f * nw;
    float b2 = ncy + 0.5f * nh;
    float b3 = ncx + 0.5f * nw;
    b0 = fminf(fmaxf(b0, 0.f), fh);
    b1 = fminf(fmaxf(b1, 0.f), fw);
    b2 = fminf(fmaxf(b2, 0.f), fh);
    b3 = fminf(fmaxf(b3, 0.f), fw);
    float hs = b2 - b0;
    float ws = b3 - b1;
    bool keep = (hs >= 16.f) && (ws >= 16.f);
    float sc = keep ? g_fg[n * NANCH + i] : -__int_as_float(0x7F800000);
    int ri = n * NANCH + i;
    ((float4*)g_roi)[ri] = make_float4(b0, b1, b2, b3);
    g_key[t] = packf(sc);
}

// ---------------- 5: per-image bitonic full sort (desc score, asc idx) ----------------
extern __shared__ unsigned char sort_sm[];
__global__ void __launch_bounds__(1024) sort_kernel() {
    unsigned int* key = (unsigned int*)sort_sm;             // 32768 * 4B
    unsigned short* sid = (unsigned short*)(key + NPAD);    // 32768 * 2B
    int n = blockIdx.x;
    int tid = threadIdx.x;
    for (int l = tid; l < NPAD; l += 1024) {
        key[l] = g_key[n * NPAD + l];
        sid[l] = (unsigned short)l;
    }
    __syncthreads();
    for (int k = 2; k <= NPAD; k <<= 1) {
        for (int j = k >> 1; j > 0; j >>= 1) {
            for (int i = tid; i < NPAD; i += 1024) {
                int ixj = i ^ j;
                if (ixj > i) {
                    unsigned int ka = key[i], kb = key[ixj];
                    unsigned short ia = sid[i], ib = sid[ixj];
                    bool aLTb = (ka < kb) || (ka == kb && ia > ib);
                    bool doswap = aLTb ^ ((i & k) != 0);
                    if (doswap) {
                        key[i] = kb; key[ixj] = ka;
                        sid[i] = ib; sid[ixj] = ia;
                    }
                }
            }
            __syncthreads();
        }
    }
    for (int l = tid; l < NPRE; l += 1024) {
        unsigned int kk = key[l];
        int ii = (int)sid[l];
        g_topkey[n * NPRE + l] = kk;
        ((float4*)g_topbox)[n * NPRE + l] = ((const float4*)g_roi)[n * NANCH + ii];
    }
}

// ---------------- 6: literal-reference NMS ----------------
#define NMS_CHUNK 6   // ceil(6000/1024)
__global__ void __launch_bounds__(1024) nms_kernel() {
    __shared__ unsigned int skey[NPRE];               // 24 KB
    __shared__ unsigned long long warpred[32];
    int n = blockIdx.x;
    int tid = threadIdx.x;
    int lane = tid & 31;
    int wid = tid >> 5;

    float4 myb[NMS_CHUNK];
#pragma unroll
    for (int k = 0; k < NMS_CHUNK; k++) {
        int l = tid + k * 1024;
        myb[k] = (l < NPRE) ? ((const float4*)g_topbox)[n * NPRE + l]
                            : make_float4(0, 0, 0, 0);
    }
    for (int l = tid; l < NPRE; l += 1024)
        skey[l] = g_topkey[n * NPRE + l];
    __syncthreads();

    for (int it = 0; it < NPOST; ++it) {
        unsigned long long best = 0ull;
#pragma unroll
        for (int k = 0; k < NMS_CHUNK; k++) {
            int l = tid + k * 1024;
            if (l < NPRE) {
                unsigned long long cand =
                    ((unsigned long long)skey[l] << 32) | (unsigned int)(NPRE - l);
                if (cand > best) best = cand;
            }
        }
#pragma unroll
        for (int o = 16; o > 0; o >>= 1) {
            unsigned long long v = __shfl_xor_sync(0xFFFFFFFFu, best, o);
            if (v > best) best = v;
        }
        if (lane == 0) warpred[wid] = best;
        __syncthreads();
        if (tid < 32) {
            unsigned long long v = warpred[tid];
#pragma unroll
            for (int o = 16; o > 0; o >>= 1) {
                unsigned long long u = __shfl_xor_sync(0xFFFFFFFFu, v, o);
                if (u > v) v = u;
            }
            if (tid == 0) warpred[0] = v;
        }
        __syncthreads();
        unsigned long long win = warpred[0];
        unsigned int wkey = (unsigned int)(win >> 32);
        int j = NPRE - (int)(win & 0xFFFFFFFFu);
        bool ok = (wkey > NEGINF_KEY);
        if (tid == 0) {
            g_sel[n * NPOST + it] = ok ? j : 0;
            g_val[n * NPOST + it] = ok ? 1 : 0;
        }
        __syncthreads();
        if (ok) {
            float4 bj = ((const float4*)g_topbox)[n * NPRE + j];
            float aj = (bj.z - bj.x) * (bj.w - bj.y);
#pragma unroll
            for (int k = 0; k < NMS_CHUNK; k++) {
                int l = tid + k * 1024;
                if (l < NPRE) {
                    float4 B = myb[k];
                    float ty = fmaxf(bj.x, B.x), tx = fmaxf(bj.y, B.y);
                    float by = fminf(bj.z, B.z), bx = fminf(bj.w, B.w);
                    float ih = fmaxf(by - ty, 0.f);
                    float iw = fmaxf(bx - tx, 0.f);
                    float inter = __fmul_rn(ih, iw);
                    float hl = B.z - B.x;
                    float wl = B.w - B.y;
                    float den = (fmaf(hl, wl, aj) - inter) + 1e-10f;
                    float iou = inter / den;
                    if (iou > 0.7f) skey[l] = NEGINF_KEY;
                }
            }
        }
        __syncthreads();
    }
}

// ---------------- 7: emit rois + roi_indices ----------------
__global__ void output_kernel(float* __restrict__ out) {
    int t = blockIdx.x * 256 + threadIdx.x;
    if (t >= NIMG * NPOST) return;
    int n = t / NPOST;
    int sel = g_sel[t];
    int val = g_val[t];
    float4 b = val ? ((const float4*)g_topbox)[n * NPRE + sel] : make_float4(0, 0, 0, 0);
    ((float4*)(out + OFF_ROIS))[t] = b;
    out[OFF_RIDX + t] = (float)n;
}

// ---------------- launch ----------------
extern "C" void kernel_launch(void* const* d_in, const int* in_sizes, int n_in,
                              void* d_out, int out_size)
{
    const float* x   = (const float*)d_in[0];
    const float* c1w = (const float*)d_in[1];
    const float* c1b = (const float*)d_in[2];
    const float* sw  = (const float*)d_in[3];
    const float* sb  = (const float*)d_in[4];
    const float* lw  = (const float*)d_in[5];
    const float* lb  = (const float*)d_in[6];
    const void*  ph  = d_in[7];
    const void*  pw  = d_in[8];
    float* out = (float*)d_out;

    wtrans_kernel<<<(CH * CH * 9 + 255) / 256, 256>>>(c1w);
    conv3x3_kernel<<<dim3(HH, 8, NIMG), 256>>>(x, c1b);
    heads_kernel<<<NIMG * 388, 256>>>(lw, lb, sw, sb, out);
    fg_kernel<<<(NIMG * NANCH + 255) / 256, 256>>>(out);
    anchor_kernel<<<(NANCH + 255) / 256, 256>>>(out);
    decode_kernel<<<(NIMG * NPAD) / 256, 256>>>(out, ph, pw);

    cudaFuncSetAttribute(sort_kernel, cudaFuncAttributeMaxDynamicSharedMemorySize,
                         NPAD * 4 + NPAD * 2);
    sort_kernel<<<NIMG, 1024, NPAD * 4 + NPAD * 2>>>();

    nms_kernel<<<NIMG, 1024>>>();
    output_kernel<<<(NIMG * NPOST + 255) / 256, 256>>>(out);
}

// round 11
// speedup vs baseline: 1.3753x; 1.3753x over previous
#include <cuda_runtime.h>
#include <cuda_bf16.h>
#include <math.h>

#define NIMG 8
#define CH 512
#define HH 50
#define WW 62
#define HW 3100            // 50*62
#define NANCH 27900        // HW*9
#define NPAD 32768
#define NPRE 6000
#define NPOST 300

// d_out layout (float32):
// [0, 892800)            rpn_locs   (8, 27900, 4)
// [892800, 1339200)      rpn_scores (8, 27900, 2)
// [1339200, 1348800)     rois       (2400, 4)
// [1348800, 1351200)     roi_indices(2400)
// [1351200, 1462800)     anchor     (27900, 4)
#define OFF_SCORES 892800
#define OFF_ROIS   1339200
#define OFF_RIDX   1348800
#define OFF_ANCH   1351200

// ---------------- scratch (device globals; no allocation) ----------------
__device__ float        g_h[NIMG * HW * CH];        // conv1 output, pixel-major [n][p][c]
__device__ float        g_wt[9 * CH * CH];          // weights transposed [tap][ci][oc]
__device__ float        g_fg[NIMG * NANCH];
__device__ float        g_roi[NIMG * NANCH * 4];
__device__ float        g_anchor[NANCH * 4];
__device__ unsigned int g_key[NIMG * NPAD];
__device__ float        g_topbox[NIMG * NPRE * 4];
__device__ unsigned int g_topkey[NIMG * NPRE];
__device__ int          g_sel[NIMG * NPOST];
__device__ int          g_val[NIMG * NPOST];

__device__ __forceinline__ unsigned int packf(float f) {
    unsigned int u = __float_as_uint(f);
    return (u & 0x80000000u) ? ~u : (u | 0x80000000u);
}
#define NEGINF_KEY 0x007FFFFFu   // packf(-inf)

__device__ __forceinline__ float read_scalar(const void* p) {
    int iv = *(const int*)p;
    float fv = *(const float*)p;
    if (iv > 0 && iv < 100000) return (float)iv;
    return fv;
}

// ---------------- 0: weight transpose [oc][ci][tap] -> [tap][ci][oc] ----------------
__global__ void wtrans_kernel(const float* __restrict__ w) {
    int t = blockIdx.x * 256 + threadIdx.x;
    if (t >= CH * CH * 9) return;
    int tap = t % 9;
    int ci  = (t / 9) % CH;
    int oc  = t / (9 * CH);
    g_wt[(tap * CH + ci) * CH + oc] = w[t];
}

// ---------------- 1: 3x3 conv + bias + ReLU ----------------
// BIT-EXACT math of the R9 passing kernel:
//   8-way CONTIGUOUS split over k=(ci,tap) (chunks of 64 ci), each chunk
//   sequential (c0 asc, ci, tap), combined pairwise:
//   ((s01+s23)+(s45+s67)).
// Implementation change vs R9: the split id v is a COMPILE-TIME constant
// (unrolled), and only one 16-reg accumulator tile is live at a time; chunk
// partials are folded with a binary-counter stack (3 levels x 16 regs).
// -> no runtime-indexed accumulator array -> no local-memory spills.
__global__ void __launch_bounds__(256) conv3x3_kernel(
    const float* __restrict__ x, const float* __restrict__ bias)
{
    __shared__ float As[8 * 9 * 64];   // [ci(8)][tap(9)][oc(64)]
    __shared__ float Bp[8 * 4 * 64];   // [ci(8)][row(4)][col(64)]

    int tid = threadIdx.x;
    int ty = tid >> 4;
    int tx = tid & 15;
    int y0  = blockIdx.x;
    int ocB = blockIdx.y * 64;
    int n   = blockIdx.z;

    float cur[4][4];
    float st0[4][4];   // pending even-chunk partial
    float st1[4][4];   // pending pair partial  (s01 / s45)
    float st2[4][4];   // pending quad partial  (s0123)
    float res[4][4];   // final

#pragma unroll
    for (int v = 0; v < 8; v++) {
#pragma unroll
        for (int i = 0; i < 4; i++)
#pragma unroll
            for (int j = 0; j < 4; j++) cur[i][j] = 0.f;

#pragma unroll 1
        for (int cb = 0; cb < 8; cb++) {
            int c0 = v * 64 + cb * 8;
            // weights [ci][tap][oc]
#pragma unroll
            for (int l = 0; l < 18; l++) {
                int t2 = tid + l * 256;
                int oc  = t2 & 63;
                int rest = t2 >> 6;
                int tap = rest % 9;
                int ci  = rest / 9;
                As[ci * 576 + tap * 64 + oc] =
                    g_wt[((size_t)tap * CH + c0 + ci) * CH + ocB + oc];
            }
            // input patch
#pragma unroll
            for (int l = 0; l < 8; l++) {
                int t2 = tid + l * 256;
                int c  = t2 & 63;
                int r  = (t2 >> 6) & 3;
                int ci = t2 >> 8;
                int yy = y0 + r - 1;
                int xx = c - 1;
                float vv = 0.f;
                if (yy >= 0 && yy < HH && xx >= 0 && xx < WW)
                    vv = x[(((size_t)n * CH + c0 + ci) * HH + yy) * WW + xx];
                Bp[ci * 256 + r * 64 + c] = vv;
            }
            __syncthreads();

#pragma unroll
            for (int ci = 0; ci < 8; ci++) {
#pragma unroll
                for (int tap = 0; tap < 9; tap++) {
                    int dy = tap / 3, dx = tap % 3;
                    const float4 a4 = *(const float4*)&As[ci * 576 + tap * 64 + ty * 4];
                    const float* brow = &Bp[ci * 256 + dy * 64 + tx * 4 + dx];
                    float b0 = brow[0], b1 = brow[1], b2 = brow[2], b3 = brow[3];
                    cur[0][0] = fmaf(a4.x, b0, cur[0][0]);
                    cur[0][1] = fmaf(a4.x, b1, cur[0][1]);
                    cur[0][2] = fmaf(a4.x, b2, cur[0][2]);
                    cur[0][3] = fmaf(a4.x, b3, cur[0][3]);
                    cur[1][0] = fmaf(a4.y, b0, cur[1][0]);
                    cur[1][1] = fmaf(a4.y, b1, cur[1][1]);
                    cur[1][2] = fmaf(a4.y, b2, cur[1][2]);
                    cur[1][3] = fmaf(a4.y, b3, cur[1][3]);
                    cur[2][0] = fmaf(a4.z, b0, cur[2][0]);
                    cur[2][1] = fmaf(a4.z, b1, cur[2][1]);
                    cur[2][2] = fmaf(a4.z, b2, cur[2][2]);
                    cur[2][3] = fmaf(a4.z, b3, cur[2][3]);
                    cur[3][0] = fmaf(a4.w, b0, cur[3][0]);
                    cur[3][1] = fmaf(a4.w, b1, cur[3][1]);
                    cur[3][2] = fmaf(a4.w, b2, cur[3][2]);
                    cur[3][3] = fmaf(a4.w, b3, cur[3][3]);
                }
            }
            __syncthreads();
        }

        // binary-counter tree combine (static, resolves at compile time):
        // pairs: s01=a0+a1, s23=a2+a3, s45=a4+a5, s67=a6+a7
        // quads: s0123=s01+s23, s4567=s45+s67 ; final res=s0123+s4567
        if ((v & 1) == 0) {
#pragma unroll
            for (int i = 0; i < 4; i++)
#pragma unroll
                for (int j = 0; j < 4; j++) st0[i][j] = cur[i][j];
        } else {
            float t01[4][4];
#pragma unroll
            for (int i = 0; i < 4; i++)
#pragma unroll
                for (int j = 0; j < 4; j++)
                    t01[i][j] = __fadd_rn(st0[i][j], cur[i][j]);
            if ((v & 3) == 1) {
#pragma unroll
                for (int i = 0; i < 4; i++)
#pragma unroll
                    for (int j = 0; j < 4; j++) st1[i][j] = t01[i][j];
            } else {
                float tq[4][4];
#pragma unroll
                for (int i = 0; i < 4; i++)
#pragma unroll
                    for (int j = 0; j < 4; j++)
                        tq[i][j] = __fadd_rn(st1[i][j], t01[i][j]);
                if (v == 3) {
#pragma unroll
                    for (int i = 0; i < 4; i++)
#pragma unroll
                        for (int j = 0; j < 4; j++) st2[i][j] = tq[i][j];
                } else {   // v == 7
#pragma unroll
                    for (int i = 0; i < 4; i++)
#pragma unroll
                        for (int j = 0; j < 4; j++)
                            res[i][j] = __fadd_rn(st2[i][j], tq[i][j]);
                }
            }
        }
    }

#pragma unroll
    for (int j = 0; j < 4; j++) {
        int px = tx * 4 + j;
        if (px >= WW) continue;
        int p = y0 * WW + px;
#pragma unroll
        for (int i = 0; i < 4; i++) {
            int oc = ocB + ty * 4 + i;
            float vv = res[i][j] + bias[oc];
            g_h[((size_t)n * HW + p) * CH + oc] = fmaxf(vv, 0.f);
        }
    }
}

// ---------------- 2: head 1x1 convs (8-way contiguous split, tree combine) ----------------
__global__ void heads_kernel(const float* __restrict__ loc_w, const float* __restrict__ loc_b,
                             const float* __restrict__ sc_w,  const float* __restrict__ sc_b,
                             float* __restrict__ out)
{
    __shared__ float hs[8 * CH];
    int g = blockIdx.x;
    int n = g / 388;
    int p0 = (g % 388) * 8;
    for (int l = threadIdx.x; l < 8 * CH; l += 256) {
        int pp = l >> 9, c = l & 511;
        int p = p0 + pp;
        hs[l] = (p < HW) ? g_h[((size_t)n * HW + p) * CH + c] : 0.f;
    }
    __syncthreads();
    for (int job = threadIdx.x; job < 432; job += 256) {
        int pp = job / 54, o = job % 54;
        int p = p0 + pp;
        if (p >= HW) continue;
        const float* wrow;
        float b;
        if (o < 36) { wrow = loc_w + o * CH; b = loc_b[o]; }
        else        { wrow = sc_w + (o - 36) * CH; b = sc_b[o - 36]; }
        const float* h = &hs[pp * CH];
        float sv[8];
#pragma unroll
        for (int v = 0; v < 8; v++) {
            float s = 0.f;
            int base = v * 64;
#pragma unroll 8
            for (int c = 0; c < 64; c++)
                s = fmaf(h[base + c], wrow[base + c], s);
            sv[v] = s;
        }
        float s01 = __fadd_rn(sv[0], sv[1]);
        float s23 = __fadd_rn(sv[2], sv[3]);
        float s45 = __fadd_rn(sv[4], sv[5]);
        float s67 = __fadd_rn(sv[6], sv[7]);
        float s = __fadd_rn(__fadd_rn(s01, s23), __fadd_rn(s45, s67)) + b;
        if (o < 36) out[(size_t)n * 111600 + p * 36 + o] = s;
        else        out[OFF_SCORES + (size_t)n * 55800 + p * 18 + (o - 36)] = s;
    }
}

// ---------------- 2b: softmax fg scores ----------------
__global__ void fg_kernel(const float* __restrict__ out) {
    int t = blockIdx.x * 256 + threadIdx.x;
    if (t >= NIMG * NANCH) return;
    int n = t / NANCH, i = t % NANCH;
    int p = i / 9, a = i % 9;
    const float* s = out + OFF_SCORES + (size_t)n * 55800 + p * 18 + a * 2;
    float s0 = s[0], s1 = s[1];
    float m = fmaxf(s0, s1);
    float e0 = expf(s0 - m);
    float e1 = expf(s1 - m);
    g_fg[t] = e1 / (e0 + e1);
}

// ---------------- 3: anchors ----------------
__global__ void anchor_kernel(float* __restrict__ out) {
    int t = blockIdx.x * 256 + threadIdx.x;
    if (t >= NANCH) return;
    int p = t / 9, a = t % 9;
    int y = p / WW, x = p - y * WW;
    int ridx = a / 3, sidx = a % 3;
    double r = (ridx == 0) ? 0.5 : ((ridx == 1) ? 1.0 : 2.0);
    double s = (sidx == 0) ? 8.0 : ((sidx == 1) ? 16.0 : 32.0);
    double hb = 16.0 * s * sqrt(r);
    double wb = 16.0 * s * sqrt(1.0 / r);
    float a0 = (float)(8.0 - hb / 2.0);
    float a1 = (float)(8.0 - wb / 2.0);
    float a2 = (float)(8.0 + hb / 2.0);
    float a3 = (float)(8.0 + wb / 2.0);
    float sy = (float)y * 16.0f, sx = (float)x * 16.0f;
    float v0 = a0 + sy, v1 = a1 + sx;
    float v2 = a2 + sy, v3 = a3 + sx;
    g_anchor[t * 4 + 0] = v0; g_anchor[t * 4 + 1] = v1;
    g_anchor[t * 4 + 2] = v2; g_anchor[t * 4 + 3] = v3;
    out[OFF_ANCH + t * 4 + 0] = v0; out[OFF_ANCH + t * 4 + 1] = v1;
    out[OFF_ANCH + t * 4 + 2] = v2; out[OFF_ANCH + t * 4 + 3] = v3;
}

// ---------------- 4: decode boxes + clip + filter + pack sort keys ----------------
__global__ void decode_kernel(const float* __restrict__ out, const void* ph, const void* pw) {
    int t = blockIdx.x * 256 + threadIdx.x;
    if (t >= NIMG * NPAD) return;
    int n = t >> 15, i = t & (NPAD - 1);
    if (i >= NANCH) { g_key[t] = 0u; return; }
    float fh = read_scalar(ph), fw = read_scalar(pw);
    const float* A = &g_anchor[i * 4];
    float ah = A[2] - A[0];
    float aw = A[3] - A[1];
    float cy = A[0] + 0.5f * ah;
    float cx = A[1] + 0.5f * aw;
    const float* L = out + (size_t)n * 111600 + (size_t)i * 4;
    float dy = L[0], dx = L[1], dh = L[2], dw = L[3];
    float ncy = dy * ah + cy;
    float ncx = dx * aw + cx;
    float nh = expf(dh) * ah;
    float nw = expf(dw) * aw;
    float b0 = ncy - 0.5f * nh;
    float b1 = ncx - 0.5f * nw;
    float b2 = ncy + 0.5f * nh;
    float b3 = ncx + 0.5f * nw;
    b0 = fminf(fmaxf(b0, 0.f), fh);
    b1 = fminf(fmaxf(b1, 0.f), fw);
    b2 = fminf(fmaxf(b2, 0.f), fh);
    b3 = fminf(fmaxf(b3, 0.f), fw);
    float hs = b2 - b0;
    float ws = b3 - b1;
    bool keep = (hs >= 16.f) && (ws >= 16.f);
    float sc = keep ? g_fg[n * NANCH + i] : -__int_as_float(0x7F800000);
    int ri = n * NANCH + i;
    ((float4*)g_roi)[ri] = make_float4(b0, b1, b2, b3);
    g_key[t] = packf(sc);
}

// ---------------- 5: per-image bitonic full sort (desc score, asc idx) ----------------
extern __shared__ unsigned char sort_sm[];
__global__ void __launch_bounds__(1024) sort_kernel() {
    unsigned int* key = (unsigned int*)sort_sm;             // 32768 * 4B
    unsigned short* sid = (unsigned short*)(key + NPAD);    // 32768 * 2B
    int n = blockIdx.x;
    int tid = threadIdx.x;
    for (int l = tid; l < NPAD; l += 1024) {
        key[l] = g_key[n * NPAD + l];
        sid[l] = (unsigned short)l;
    }
    __syncthreads();
    for (int k = 2; k <= NPAD; k <<= 1) {
        for (int j = k >> 1; j > 0; j >>= 1) {
            for (int i = tid; i < NPAD; i += 1024) {
                int ixj = i ^ j;
                if (ixj > i) {
                    unsigned int ka = key[i], kb = key[ixj];
                    unsigned short ia = sid[i], ib = sid[ixj];
                    bool aLTb = (ka < kb) || (ka == kb && ia > ib);
                    bool doswap = aLTb ^ ((i & k) != 0);
                    if (doswap) {
                        key[i] = kb; key[ixj] = ka;
                        sid[i] = ib; sid[ixj] = ia;
                    }
                }
            }
            __syncthreads();
        }
    }
    for (int l = tid; l < NPRE; l += 1024) {
        unsigned int kk = key[l];
        int ii = (int)sid[l];
        g_topkey[n * NPRE + l] = kk;
        ((float4*)g_topbox)[n * NPRE + l] = ((const float4*)g_roi)[n * NANCH + ii];
    }
}

// ---------------- 6: literal-reference NMS ----------------
#define NMS_CHUNK 6   // ceil(6000/1024)
__global__ void __launch_bounds__(1024) nms_kernel() {
    __shared__ unsigned int skey[NPRE];               // 24 KB
    __shared__ unsigned long long warpred[32];
    int n = blockIdx.x;
    int tid = threadIdx.x;
    int lane = tid & 31;
    int wid = tid >> 5;

    float4 myb[NMS_CHUNK];
#pragma unroll
    for (int k = 0; k < NMS_CHUNK; k++) {
        int l = tid + k * 1024;
        myb[k] = (l < NPRE) ? ((const float4*)g_topbox)[n * NPRE + l]
                            : make_float4(0, 0, 0, 0);
    }
    for (int l = tid; l < NPRE; l += 1024)
        skey[l] = g_topkey[n * NPRE + l];
    __syncthreads();

    for (int it = 0; it < NPOST; ++it) {
        unsigned long long best = 0ull;
#pragma unroll
        for (int k = 0; k < NMS_CHUNK; k++) {
            int l = tid + k * 1024;
            if (l < NPRE) {
                unsigned long long cand =
                    ((unsigned long long)skey[l] << 32) | (unsigned int)(NPRE - l);
                if (cand > best) best = cand;
            }
        }
#pragma unroll
        for (int o = 16; o > 0; o >>= 1) {
            unsigned long long v = __shfl_xor_sync(0xFFFFFFFFu, best, o);
            if (v > best) best = v;
        }
        if (lane == 0) warpred[wid] = best;
        __syncthreads();
        if (tid < 32) {
            unsigned long long v = warpred[tid];
#pragma unroll
            for (int o = 16; o > 0; o >>= 1) {
                unsigned long long u = __shfl_xor_sync(0xFFFFFFFFu, v, o);
                if (u > v) v = u;
            }
            if (tid == 0) warpred[0] = v;
        }
        __syncthreads();
        unsigned long long win = warpred[0];
        unsigned int wkey = (unsigned int)(win >> 32);
        int j = NPRE - (int)(win & 0xFFFFFFFFu);
        bool ok = (wkey > NEGINF_KEY);
        if (tid == 0) {
            g_sel[n * NPOST + it] = ok ? j : 0;
            g_val[n * NPOST + it] = ok ? 1 : 0;
        }
        __syncthreads();
        if (ok) {
            float4 bj = ((const float4*)g_topbox)[n * NPRE + j];
            float aj = (bj.z - bj.x) * (bj.w - bj.y);
#pragma unroll
            for (int k = 0; k < NMS_CHUNK; k++) {
                int l = tid + k * 1024;
                if (l < NPRE) {
                    float4 B = myb[k];
                    float ty = fmaxf(bj.x, B.x), tx = fmaxf(bj.y, B.y);
                    float by = fminf(bj.z, B.z), bx = fminf(bj.w, B.w);
                    float ih = fmaxf(by - ty, 0.f);
                    float iw = fmaxf(bx - tx, 0.f);
                    float inter = __fmul_rn(ih, iw);
                    float hl = B.z - B.x;
                    float wl = B.w - B.y;
                    float den = (fmaf(hl, wl, aj) - inter) + 1e-10f;
                    float iou = inter / den;
                    if (iou > 0.7f) skey[l] = NEGINF_KEY;
                }
            }
        }
        __syncthreads();
    }
}

// ---------------- 7: emit rois + roi_indices ----------------
__global__ void output_kernel(float* __restrict__ out) {
    int t = blockIdx.x * 256 + threadIdx.x;
    if (t >= NIMG * NPOST) return;
    int n = t / NPOST;
    int sel = g_sel[t];
    int val = g_val[t];
    float4 b = val ? ((const float4*)g_topbox)[n * NPRE + sel] : make_float4(0, 0, 0, 0);
    ((float4*)(out + OFF_ROIS))[t] = b;
    out[OFF_RIDX + t] = (float)n;
}

// ---------------- launch ----------------
extern "C" void kernel_launch(void* const* d_in, const int* in_sizes, int n_in,
                              void* d_out, int out_size)
{
    const float* x   = (const float*)d_in[0];
    const float* c1w = (const float*)d_in[1];
    const float* c1b = (const float*)d_in[2];
    const float* sw  = (const float*)d_in[3];
    const float* sb  = (const float*)d_in[4];
    const float* lw  = (const float*)d_in[5];
    const float* lb  = (const float*)d_in[6];
    const void*  ph  = d_in[7];
    const void*  pw  = d_in[8];
    float* out = (float*)d_out;

    wtrans_kernel<<<(CH * CH * 9 + 255) / 256, 256>>>(c1w);
    conv3x3_kernel<<<dim3(HH, 8, NIMG), 256>>>(x, c1b);
    heads_kernel<<<NIMG * 388, 256>>>(lw, lb, sw, sb, out);
    fg_kernel<<<(NIMG * NANCH + 255) / 256, 256>>>(out);
    anchor_kernel<<<(NANCH + 255) / 256, 256>>>(out);
    decode_kernel<<<(NIMG * NPAD) / 256, 256>>>(out, ph, pw);

    cudaFuncSetAttribute(sort_kernel, cudaFuncAttributeMaxDynamicSharedMemorySize,
                         NPAD * 4 + NPAD * 2);
    sort_kernel<<<NIMG, 1024, NPAD * 4 + NPAD * 2>>>();

    nms_kernel<<<NIMG, 1024>>>();
    output_kernel<<<(NIMG * NPOST + 255) / 256, 256>>>(out);
}

// round 12
// speedup vs baseline: 1.3915x; 1.0118x over previous
#include <cuda_runtime.h>
#include <cuda_bf16.h>
#include <math.h>

#define NIMG 8
#define CH 512
#define HH 50
#define WW 62
#define HW 3100            // 50*62
#define NANCH 27900        // HW*9
#define NPAD 32768
#define NPRE 6000
#define NPOST 300

// d_out layout (float32):
// [0, 892800)            rpn_locs   (8, 27900, 4)
// [892800, 1339200)      rpn_scores (8, 27900, 2)
// [1339200, 1348800)     rois       (2400, 4)
// [1348800, 1351200)     roi_indices(2400)
// [1351200, 1462800)     anchor     (27900, 4)
#define OFF_SCORES 892800
#define OFF_ROIS   1339200
#define OFF_RIDX   1348800
#define OFF_ANCH   1351200

// ---------------- scratch (device globals; no allocation) ----------------
__device__ float        g_h[NIMG * HW * CH];        // conv1 output, pixel-major [n][p][c]
__device__ float        g_wt[9 * CH * CH];          // weights transposed [tap][ci][oc]
__device__ float        g_fg[NIMG * NANCH];
__device__ float        g_roi[NIMG * NANCH * 4];
__device__ float        g_anchor[NANCH * 4];
__device__ unsigned int g_key[NIMG * NPAD];
__device__ float        g_topbox[NIMG * NPRE * 4];
__device__ unsigned int g_topkey[NIMG * NPRE];
__device__ int          g_sel[NIMG * NPOST];
__device__ int          g_val[NIMG * NPOST];

__device__ __forceinline__ unsigned int packf(float f) {
    unsigned int u = __float_as_uint(f);
    return (u & 0x80000000u) ? ~u : (u | 0x80000000u);
}
#define NEGINF_KEY 0x007FFFFFu   // packf(-inf)

__device__ __forceinline__ float read_scalar(const void* p) {
    int iv = *(const int*)p;
    float fv = *(const float*)p;
    if (iv > 0 && iv < 100000) return (float)iv;
    return fv;
}

// ---------------- 0: weight transpose [oc][ci][tap] -> [tap][ci][oc] ----------------
__global__ void wtrans_kernel(const float* __restrict__ w) {
    int t = blockIdx.x * 256 + threadIdx.x;
    if (t >= CH * CH * 9) return;
    int tap = t % 9;
    int ci  = (t / 9) % CH;
    int oc  = t / (9 * CH);
    g_wt[(tap * CH + ci) * CH + oc] = w[t];
}

// ---------------- 1: 3x3 conv + bias + ReLU ----------------
// BIT-EXACT math of the R9 passing kernel: 8-way CONTIGUOUS split over
// k=(ci,tap) (chunks of 64 ci), each chunk sequential (c0 asc, ci, tap),
// combined pairwise ((s01+s23)+(s45+s67)).
// Code shape (the R10/R11 lessons):
//  - ONE copy of the 1152-FMA inner body (c0 loop NOT unrolled) -> fits I$.
//  - accumulators statically indexed registers; the tree fold runs as
//    runtime-branched code only 8 times (at each 64-ci chunk boundary).
__global__ void __launch_bounds__(256) conv3x3_kernel(
    const float* __restrict__ x, const float* __restrict__ bias)
{
    __shared__ float As[8 * 9 * 64];   // [ci(8)][tap(9)][oc(64)]
    __shared__ float Bp[8 * 4 * 64];   // [ci(8)][row(4)][col(64)]

    int tid = threadIdx.x;
    int ty = tid >> 4;
    int tx = tid & 15;
    int y0  = blockIdx.x;
    int ocB = blockIdx.y * 64;
    int n   = blockIdx.z;

    float cur[4][4];
    float st0[4][4];
    float st1[4][4];
    float st2[4][4];
    float res[4][4];

#pragma unroll
    for (int i = 0; i < 4; i++)
#pragma unroll
        for (int j = 0; j < 4; j++) cur[i][j] = 0.f;

#pragma unroll 1
    for (int c0 = 0; c0 < CH; c0 += 8) {
        // weights [ci][tap][oc]
#pragma unroll
        for (int l = 0; l < 18; l++) {
            int t2 = tid + l * 256;
            int oc  = t2 & 63;
            int rest = t2 >> 6;
            int tap = rest % 9;
            int ci  = rest / 9;
            As[ci * 576 + tap * 64 + oc] =
                g_wt[((size_t)tap * CH + c0 + ci) * CH + ocB + oc];
        }
        // input patch
#pragma unroll
        for (int l = 0; l < 8; l++) {
            int t2 = tid + l * 256;
            int c  = t2 & 63;
            int r  = (t2 >> 6) & 3;
            int ci = t2 >> 8;
            int yy = y0 + r - 1;
            int xx = c - 1;
            float vv = 0.f;
            if (yy >= 0 && yy < HH && xx >= 0 && xx < WW)
                vv = x[(((size_t)n * CH + c0 + ci) * HH + yy) * WW + xx];
            Bp[ci * 256 + r * 64 + c] = vv;
        }
        __syncthreads();

#pragma unroll
        for (int ci = 0; ci < 8; ci++) {
#pragma unroll
            for (int tap = 0; tap < 9; tap++) {
                int dy = tap / 3, dx = tap % 3;
                const float4 a4 = *(const float4*)&As[ci * 576 + tap * 64 + ty * 4];
                const float* brow = &Bp[ci * 256 + dy * 64 + tx * 4 + dx];
                float b0 = brow[0], b1 = brow[1], b2 = brow[2], b3 = brow[3];
                cur[0][0] = fmaf(a4.x, b0, cur[0][0]);
                cur[0][1] = fmaf(a4.x, b1, cur[0][1]);
                cur[0][2] = fmaf(a4.x, b2, cur[0][2]);
                cur[0][3] = fmaf(a4.x, b3, cur[0][3]);
                cur[1][0] = fmaf(a4.y, b0, cur[1][0]);
                cur[1][1] = fmaf(a4.y, b1, cur[1][1]);
                cur[1][2] = fmaf(a4.y, b2, cur[1][2]);
                cur[1][3] = fmaf(a4.y, b3, cur[1][3]);
                cur[2][0] = fmaf(a4.z, b0, cur[2][0]);
                cur[2][1] = fmaf(a4.z, b1, cur[2][1]);
                cur[2][2] = fmaf(a4.z, b2, cur[2][2]);
                cur[2][3] = fmaf(a4.z, b3, cur[2][3]);
                cur[3][0] = fmaf(a4.w, b0, cur[3][0]);
                cur[3][1] = fmaf(a4.w, b1, cur[3][1]);
                cur[3][2] = fmaf(a4.w, b2, cur[3][2]);
                cur[3][3] = fmaf(a4.w, b3, cur[3][3]);
            }
        }
        __syncthreads();

        // chunk boundary: fold `cur` into the pairwise tree, reset it.
        if ((c0 & 56) == 56) {
            int v = c0 >> 6;
            if ((v & 1) == 0) {
#pragma unroll
                for (int i = 0; i < 4; i++)
#pragma unroll
                    for (int j = 0; j < 4; j++) st0[i][j] = cur[i][j];
            } else {
                float t01[4][4];
#pragma unroll
                for (int i = 0; i < 4; i++)
#pragma unroll
                    for (int j = 0; j < 4; j++)
                        t01[i][j] = __fadd_rn(st0[i][j], cur[i][j]);
                if ((v & 3) == 1) {
#pragma unroll
                    for (int i = 0; i < 4; i++)
#pragma unroll
                        for (int j = 0; j < 4; j++) st1[i][j] = t01[i][j];
                } else {
                    float tq[4][4];
#pragma unroll
                    for (int i = 0; i < 4; i++)
#pragma unroll
                        for (int j = 0; j < 4; j++)
                            tq[i][j] = __fadd_rn(st1[i][j], t01[i][j]);
                    if (v == 3) {
#pragma unroll
                        for (int i = 0; i < 4; i++)
#pragma unroll
                            for (int j = 0; j < 4; j++) st2[i][j] = tq[i][j];
                    } else {   // v == 7
#pragma unroll
                        for (int i = 0; i < 4; i++)
#pragma unroll
                            for (int j = 0; j < 4; j++)
                                res[i][j] = __fadd_rn(st2[i][j], tq[i][j]);
                    }
                }
            }
#pragma unroll
            for (int i = 0; i < 4; i++)
#pragma unroll
                for (int j = 0; j < 4; j++) cur[i][j] = 0.f;
        }
    }

#pragma unroll
    for (int j = 0; j < 4; j++) {
        int px = tx * 4 + j;
        if (px >= WW) continue;
        int p = y0 * WW + px;
#pragma unroll
        for (int i = 0; i < 4; i++) {
            int oc = ocB + ty * 4 + i;
            float vv = res[i][j] + bias[oc];
            g_h[((size_t)n * HW + p) * CH + oc] = fmaxf(vv, 0.f);
        }
    }
}

// ---------------- 2: head 1x1 convs (8-way contiguous split, tree combine) ----------------
__global__ void heads_kernel(const float* __restrict__ loc_w, const float* __restrict__ loc_b,
                             const float* __restrict__ sc_w,  const float* __restrict__ sc_b,
                             float* __restrict__ out)
{
    __shared__ float hs[8 * CH];
    int g = blockIdx.x;
    int n = g / 388;
    int p0 = (g % 388) * 8;
    for (int l = threadIdx.x; l < 8 * CH; l += 256) {
        int pp = l >> 9, c = l & 511;
        int p = p0 + pp;
        hs[l] = (p < HW) ? g_h[((size_t)n * HW + p) * CH + c] : 0.f;
    }
    __syncthreads();
    for (int job = threadIdx.x; job < 432; job += 256) {
        int pp = job / 54, o = job % 54;
        int p = p0 + pp;
        if (p >= HW) continue;
        const float* wrow;
        float b;
        if (o < 36) { wrow = loc_w + o * CH; b = loc_b[o]; }
        else        { wrow = sc_w + (o - 36) * CH; b = sc_b[o - 36]; }
        const float* h = &hs[pp * CH];
        float sv[8];
#pragma unroll
        for (int v = 0; v < 8; v++) {
            float s = 0.f;
            int base = v * 64;
#pragma unroll 8
            for (int c = 0; c < 64; c++)
                s = fmaf(h[base + c], wrow[base + c], s);
            sv[v] = s;
        }
        float s01 = __fadd_rn(sv[0], sv[1]);
        float s23 = __fadd_rn(sv[2], sv[3]);
        float s45 = __fadd_rn(sv[4], sv[5]);
        float s67 = __fadd_rn(sv[6], sv[7]);
        float s = __fadd_rn(__fadd_rn(s01, s23), __fadd_rn(s45, s67)) + b;
        if (o < 36) out[(size_t)n * 111600 + p * 36 + o] = s;
        else        out[OFF_SCORES + (size_t)n * 55800 + p * 18 + (o - 36)] = s;
    }
}

// ---------------- 2b: softmax fg scores ----------------
__global__ void fg_kernel(const float* __restrict__ out) {
    int t = blockIdx.x * 256 + threadIdx.x;
    if (t >= NIMG * NANCH) return;
    int n = t / NANCH, i = t % NANCH;
    int p = i / 9, a = i % 9;
    const float* s = out + OFF_SCORES + (size_t)n * 55800 + p * 18 + a * 2;
    float s0 = s[0], s1 = s[1];
    float m = fmaxf(s0, s1);
    float e0 = expf(s0 - m);
    float e1 = expf(s1 - m);
    g_fg[t] = e1 / (e0 + e1);
}

// ---------------- 3: anchors ----------------
__global__ void anchor_kernel(float* __restrict__ out) {
    int t = blockIdx.x * 256 + threadIdx.x;
    if (t >= NANCH) return;
    int p = t / 9, a = t % 9;
    int y = p / WW, x = p - y * WW;
    int ridx = a / 3, sidx = a % 3;
    double r = (ridx == 0) ? 0.5 : ((ridx == 1) ? 1.0 : 2.0);
    double s = (sidx == 0) ? 8.0 : ((sidx == 1) ? 16.0 : 32.0);
    double hb = 16.0 * s * sqrt(r);
    double wb = 16.0 * s * sqrt(1.0 / r);
    float a0 = (float)(8.0 - hb / 2.0);
    float a1 = (float)(8.0 - wb / 2.0);
    float a2 = (float)(8.0 + hb / 2.0);
    float a3 = (float)(8.0 + wb / 2.0);
    float sy = (float)y * 16.0f, sx = (float)x * 16.0f;
    float v0 = a0 + sy, v1 = a1 + sx;
    float v2 = a2 + sy, v3 = a3 + sx;
    g_anchor[t * 4 + 0] = v0; g_anchor[t * 4 + 1] = v1;
    g_anchor[t * 4 + 2] = v2; g_anchor[t * 4 + 3] = v3;
    out[OFF_ANCH + t * 4 + 0] = v0; out[OFF_ANCH + t * 4 + 1] = v1;
    out[OFF_ANCH + t * 4 + 2] = v2; out[OFF_ANCH + t * 4 + 3] = v3;
}

// ---------------- 4: decode boxes + clip + filter + pack sort keys ----------------
__global__ void decode_kernel(const float* __restrict__ out, const void* ph, const void* pw) {
    int t = blockIdx.x * 256 + threadIdx.x;
    if (t >= NIMG * NPAD) return;
    int n = t >> 15, i = t & (NPAD - 1);
    if (i >= NANCH) { g_key[t] = 0u; return; }
    float fh = read_scalar(ph), fw = read_scalar(pw);
    const float* A = &g_anchor[i * 4];
    float ah = A[2] - A[0];
    float aw = A[3] - A[1];
    float cy = A[0] + 0.5f * ah;
    float cx = A[1] + 0.5f * aw;
    const float* L = out + (size_t)n * 111600 + (size_t)i * 4;
    float dy = L[0], dx = L[1], dh = L[2], dw = L[3];
    float ncy = dy * ah + cy;
    float ncx = dx * aw + cx;
    float nh = expf(dh) * ah;
    float nw = expf(dw) * aw;
    float b0 = ncy - 0.5f * nh;
    float b1 = ncx - 0.5f * nw;
    float b2 = ncy + 0.5f * nh;
    float b3 = ncx + 0.5f * nw;
    b0 = fminf(fmaxf(b0, 0.f), fh);
    b1 = fminf(fmaxf(b1, 0.f), fw);
    b2 = fminf(fmaxf(b2, 0.f), fh);
    b3 = fminf(fmaxf(b3, 0.f), fw);
    float hs = b2 - b0;
    float ws = b3 - b1;
    bool keep = (hs >= 16.f) && (ws >= 16.f);
    float sc = keep ? g_fg[n * NANCH + i] : -__int_as_float(0x7F800000);
    int ri = n * NANCH + i;
    ((float4*)g_roi)[ri] = make_float4(b0, b1, b2, b3);
    g_key[t] = packf(sc);
}

// ---------------- 5: per-image bitonic full sort (desc score, asc idx) ----------------
extern __shared__ unsigned char sort_sm[];
__global__ void __launch_bounds__(1024) sort_kernel() {
    unsigned int* key = (unsigned int*)sort_sm;             // 32768 * 4B
    unsigned short* sid = (unsigned short*)(key + NPAD);    // 32768 * 2B
    int n = blockIdx.x;
    int tid = threadIdx.x;
    for (int l = tid; l < NPAD; l += 1024) {
        key[l] = g_key[n * NPAD + l];
        sid[l] = (unsigned short)l;
    }
    __syncthreads();
    for (int k = 2; k <= NPAD; k <<= 1) {
        for (int j = k >> 1; j > 0; j >>= 1) {
            for (int i = tid; i < NPAD; i += 1024) {
                int ixj = i ^ j;
                if (ixj > i) {
                    unsigned int ka = key[i], kb = key[ixj];
                    unsigned short ia = sid[i], ib = sid[ixj];
                    bool aLTb = (ka < kb) || (ka == kb && ia > ib);
                    bool doswap = aLTb ^ ((i & k) != 0);
                    if (doswap) {
                        key[i] = kb; key[ixj] = ka;
                        sid[i] = ib; sid[ixj] = ia;
                    }
                }
            }
            __syncthreads();
        }
    }
    for (int l = tid; l < NPRE; l += 1024) {
        unsigned int kk = key[l];
        int ii = (int)sid[l];
        g_topkey[n * NPRE + l] = kk;
        ((float4*)g_topbox)[n * NPRE + l] = ((const float4*)g_roi)[n * NANCH + ii];
    }
}

// ---------------- 6: literal-reference NMS ----------------
#define NMS_CHUNK 6   // ceil(6000/1024)
__global__ void __launch_bounds__(1024) nms_kernel() {
    __shared__ unsigned int skey[NPRE];               // 24 KB
    __shared__ unsigned long long warpred[32];
    int n = blockIdx.x;
    int tid = threadIdx.x;
    int lane = tid & 31;
    int wid = tid >> 5;

    float4 myb[NMS_CHUNK];
#pragma unroll
    for (int k = 0; k < NMS_CHUNK; k++) {
        int l = tid + k * 1024;
        myb[k] = (l < NPRE) ? ((const float4*)g_topbox)[n * NPRE + l]
                            : make_float4(0, 0, 0, 0);
    }
    for (int l = tid; l < NPRE; l += 1024)
        skey[l] = g_topkey[n * NPRE + l];
    __syncthreads();

    for (int it = 0; it < NPOST; ++it) {
        unsigned long long best = 0ull;
#pragma unroll
        for (int k = 0; k < NMS_CHUNK; k++) {
            int l = tid + k * 1024;
            if (l < NPRE) {
                unsigned long long cand =
                    ((unsigned long long)skey[l] << 32) | (unsigned int)(NPRE - l);
                if (cand > best) best = cand;
            }
        }
#pragma unroll
        for (int o = 16; o > 0; o >>= 1) {
            unsigned long long v = __shfl_xor_sync(0xFFFFFFFFu, best, o);
            if (v > best) best = v;
        }
        if (lane == 0) warpred[wid] = best;
        __syncthreads();
        if (tid < 32) {
            unsigned long long v = warpred[tid];
#pragma unroll
            for (int o = 16; o > 0; o >>= 1) {
                unsigned long long u = __shfl_xor_sync(0xFFFFFFFFu, v, o);
                if (u > v) v = u;
            }
            if (tid == 0) warpred[0] = v;
        }
        __syncthreads();
        unsigned long long win = warpred[0];
        unsigned int wkey = (unsigned int)(win >> 32);
        int j = NPRE - (int)(win & 0xFFFFFFFFu);
        bool ok = (wkey > NEGINF_KEY);
        if (tid == 0) {
            g_sel[n * NPOST + it] = ok ? j : 0;
            g_val[n * NPOST + it] = ok ? 1 : 0;
        }
        __syncthreads();
        if (ok) {
            float4 bj = ((const float4*)g_topbox)[n * NPRE + j];
            float aj = (bj.z - bj.x) * (bj.w - bj.y);
#pragma unroll
            for (int k = 0; k < NMS_CHUNK; k++) {
                int l = tid + k * 1024;
                if (l < NPRE) {
                    float4 B = myb[k];
                    float ty = fmaxf(bj.x, B.x), tx = fmaxf(bj.y, B.y);
                    float by = fminf(bj.z, B.z), bx = fminf(bj.w, B.w);
                    float ih = fmaxf(by - ty, 0.f);
                    float iw = fmaxf(bx - tx, 0.f);
                    float inter = __fmul_rn(ih, iw);
                    float hl = B.z - B.x;
                    float wl = B.w - B.y;
                    float den = (fmaf(hl, wl, aj) - inter) + 1e-10f;
                    float iou = inter / den;
                    if (iou > 0.7f) skey[l] = NEGINF_KEY;
                }
            }
        }
        __syncthreads();
    }
}

// ---------------- 7: emit rois + roi_indices ----------------
__global__ void output_kernel(float* __restrict__ out) {
    int t = blockIdx.x * 256 + threadIdx.x;
    if (t >= NIMG * NPOST) return;
    int n = t / NPOST;
    int sel = g_sel[t];
    int val = g_val[t];
    float4 b = val ? ((const float4*)g_topbox)[n * NPRE + sel] : make_float4(0, 0, 0, 0);
    ((float4*)(out + OFF_ROIS))[t] = b;
    out[OFF_RIDX + t] = (float)n;
}

// ---------------- launch ----------------
extern "C" void kernel_launch(void* const* d_in, const int* in_sizes, int n_in,
                              void* d_out, int out_size)
{
    const float* x   = (const float*)d_in[0];
    const float* c1w = (const float*)d_in[1];
    const float* c1b = (const float*)d_in[2];
    const float* sw  = (const float*)d_in[3];
    const float* sb  = (const float*)d_in[4];
    const float* lw  = (const float*)d_in[5];
    const float* lb  = (const float*)d_in[6];
    const void*  ph  = d_in[7];
    const void*  pw  = d_in[8];
    float* out = (float*)d_out;

    wtrans_kernel<<<(CH * CH * 9 + 255) / 256, 256>>>(c1w);
    conv3x3_kernel<<<dim3(HH, 8, NIMG), 256>>>(x, c1b);
    heads_kernel<<<NIMG * 388, 256>>>(lw, lb, sw, sb, out);
    fg_kernel<<<(NIMG * NANCH + 255) / 256, 256>>>(out);
    anchor_kernel<<<(NANCH + 255) / 256, 256>>>(out);
    decode_kernel<<<(NIMG * NPAD) / 256, 256>>>(out, ph, pw);

    cudaFuncSetAttribute(sort_kernel, cudaFuncAttributeMaxDynamicSharedMemorySize,
                         NPAD * 4 + NPAD * 2);
    sort_kernel<<<NIMG, 1024, NPAD * 4 + NPAD * 2>>>();

    nms_kernel<<<NIMG, 1024>>>();
    output_kernel<<<(NIMG * NPOST + 255) / 256, 256>>>(out);
}

// round 13
// speedup vs baseline: 1.6315x; 1.1725x over previous
#include <cuda_runtime.h>
#include <cuda_bf16.h>
#include <math.h>

#define NIMG 8
#define CH 512
#define HH 50
#define WW 62
#define HW 3100            // 50*62
#define NANCH 27900        // HW*9
#define NPAD 32768
#define NPRE 6000
#define NPOST 300

#define OFF_SCORES 892800
#define OFF_ROIS   1339200
#define OFF_RIDX   1348800
#define OFF_ANCH   1351200

// ---------------- scratch (device globals; no allocation) ----------------
__device__ float              g_h[NIMG * HW * CH];
__device__ float              g_wt[9 * CH * CH];
__device__ float              g_fg[NIMG * NANCH];
__device__ float              g_roi[NIMG * NANCH * 4];
__device__ float              g_anchor[NANCH * 4];
__device__ unsigned long long g_skey[NIMG * NPAD];   // packed (key<<16)|(NPAD-1-idx)
__device__ float              g_topbox[NIMG * NPRE * 4];
__device__ unsigned int       g_topkey[NIMG * NPRE];
__device__ int                g_sel[NIMG * NPOST];
__device__ int                g_val[NIMG * NPOST];

__device__ __forceinline__ unsigned int packf(float f) {
    unsigned int u = __float_as_uint(f);
    return (u & 0x80000000u) ? ~u : (u | 0x80000000u);
}
#define NEGINF_KEY 0x007FFFFFu   // packf(-inf)

__device__ __forceinline__ float read_scalar(const void* p) {
    int iv = *(const int*)p;
    float fv = *(const float*)p;
    if (iv > 0 && iv < 100000) return (float)iv;
    return fv;
}

// ---------------- 0: weight transpose ----------------
__global__ void wtrans_kernel(const float* __restrict__ w) {
    int t = blockIdx.x * 256 + threadIdx.x;
    if (t >= CH * CH * 9) return;
    int tap = t % 9;
    int ci  = (t / 9) % CH;
    int oc  = t / (9 * CH);
    g_wt[(tap * CH + ci) * CH + oc] = w[t];
}

// ---------------- 1: 3x3 conv + bias + ReLU (R9 verbatim — fastest measured) ----------------
__global__ void __launch_bounds__(256) conv3x3_kernel(
    const float* __restrict__ x, const float* __restrict__ bias)
{
    __shared__ float As[8 * 9 * 64];
    __shared__ float Bp[8 * 4 * 64];

    int tid = threadIdx.x;
    int ty = tid >> 4;
    int tx = tid & 15;
    int y0  = blockIdx.x;
    int ocB = blockIdx.y * 64;
    int n   = blockIdx.z;

    float acc[8][4][4];
#pragma unroll
    for (int v = 0; v < 8; v++)
#pragma unroll
        for (int i = 0; i < 4; i++)
#pragma unroll
            for (int j = 0; j < 4; j++) acc[v][i][j] = 0.f;

    for (int c0 = 0; c0 < CH; c0 += 8) {
        int v = c0 >> 6;
#pragma unroll
        for (int l = 0; l < 18; l++) {
            int t2 = tid + l * 256;
            int oc  = t2 & 63;
            int rest = t2 >> 6;
            int tap = rest % 9;
            int ci  = rest / 9;
            As[ci * 576 + tap * 64 + oc] =
                g_wt[((size_t)tap * CH + c0 + ci) * CH + ocB + oc];
        }
#pragma unroll
        for (int l = 0; l < 8; l++) {
            int t2 = tid + l * 256;
            int c  = t2 & 63;
            int r  = (t2 >> 6) & 3;
            int ci = t2 >> 8;
            int yy = y0 + r - 1;
            int xx = c - 1;
            float vv = 0.f;
            if (yy >= 0 && yy < HH && xx >= 0 && xx < WW)
                vv = x[(((size_t)n * CH + c0 + ci) * HH + yy) * WW + xx];
            Bp[ci * 256 + r * 64 + c] = vv;
        }
        __syncthreads();

#pragma unroll
        for (int ci = 0; ci < 8; ci++) {
#pragma unroll
            for (int tap = 0; tap < 9; tap++) {
                int dy = tap / 3, dx = tap % 3;
                const float4 a4 = *(const float4*)&As[ci * 576 + tap * 64 + ty * 4];
                const float* brow = &Bp[ci * 256 + dy * 64 + tx * 4 + dx];
                float b0 = brow[0], b1 = brow[1], b2 = brow[2], b3 = brow[3];
                acc[v][0][0] = fmaf(a4.x, b0, acc[v][0][0]);
                acc[v][0][1] = fmaf(a4.x, b1, acc[v][0][1]);
                acc[v][0][2] = fmaf(a4.x, b2, acc[v][0][2]);
                acc[v][0][3] = fmaf(a4.x, b3, acc[v][0][3]);
                acc[v][1][0] = fmaf(a4.y, b0, acc[v][1][0]);
                acc[v][1][1] = fmaf(a4.y, b1, acc[v][1][1]);
                acc[v][1][2] = fmaf(a4.y, b2, acc[v][1][2]);
                acc[v][1][3] = fmaf(a4.y, b3, acc[v][1][3]);
                acc[v][2][0] = fmaf(a4.z, b0, acc[v][2][0]);
                acc[v][2][1] = fmaf(a4.z, b1, acc[v][2][1]);
                acc[v][2][2] = fmaf(a4.z, b2, acc[v][2][2]);
                acc[v][2][3] = fmaf(a4.z, b3, acc[v][2][3]);
                acc[v][3][0] = fmaf(a4.w, b0, acc[v][3][0]);
                acc[v][3][1] = fmaf(a4.w, b1, acc[v][3][1]);
                acc[v][3][2] = fmaf(a4.w, b2, acc[v][3][2]);
                acc[v][3][3] = fmaf(a4.w, b3, acc[v][3][3]);
            }
        }
        __syncthreads();
    }

#pragma unroll
    for (int j = 0; j < 4; j++) {
        int px = tx * 4 + j;
        if (px >= WW) continue;
        int p = y0 * WW + px;
#pragma unroll
        for (int i = 0; i < 4; i++) {
            int oc = ocB + ty * 4 + i;
            float s01 = __fadd_rn(acc[0][i][j], acc[1][i][j]);
            float s23 = __fadd_rn(acc[2][i][j], acc[3][i][j]);
            float s45 = __fadd_rn(acc[4][i][j], acc[5][i][j]);
            float s67 = __fadd_rn(acc[6][i][j], acc[7][i][j]);
            float r = __fadd_rn(__fadd_rn(s01, s23), __fadd_rn(s45, s67));
            float vv = r + bias[oc];
            g_h[((size_t)n * HW + p) * CH + oc] = fmaxf(vv, 0.f);
        }
    }
}

// ---------------- 2: head 1x1 convs ----------------
__global__ void heads_kernel(const float* __restrict__ loc_w, const float* __restrict__ loc_b,
                             const float* __restrict__ sc_w,  const float* __restrict__ sc_b,
                             float* __restrict__ out)
{
    __shared__ float hs[8 * CH];
    int g = blockIdx.x;
    int n = g / 388;
    int p0 = (g % 388) * 8;
    for (int l = threadIdx.x; l < 8 * CH; l += 256) {
        int pp = l >> 9, c = l & 511;
        int p = p0 + pp;
        hs[l] = (p < HW) ? g_h[((size_t)n * HW + p) * CH + c] : 0.f;
    }
    __syncthreads();
    for (int job = threadIdx.x; job < 432; job += 256) {
        int pp = job / 54, o = job % 54;
        int p = p0 + pp;
        if (p >= HW) continue;
        const float* wrow;
        float b;
        if (o < 36) { wrow = loc_w + o * CH; b = loc_b[o]; }
        else        { wrow = sc_w + (o - 36) * CH; b = sc_b[o - 36]; }
        const float* h = &hs[pp * CH];
        float sv[8];
#pragma unroll
        for (int v = 0; v < 8; v++) {
            float s = 0.f;
            int base = v * 64;
#pragma unroll 8
            for (int c = 0; c < 64; c++)
                s = fmaf(h[base + c], wrow[base + c], s);
            sv[v] = s;
        }
        float s01 = __fadd_rn(sv[0], sv[1]);
        float s23 = __fadd_rn(sv[2], sv[3]);
        float s45 = __fadd_rn(sv[4], sv[5]);
        float s67 = __fadd_rn(sv[6], sv[7]);
        float s = __fadd_rn(__fadd_rn(s01, s23), __fadd_rn(s45, s67)) + b;
        if (o < 36) out[(size_t)n * 111600 + p * 36 + o] = s;
        else        out[OFF_SCORES + (size_t)n * 55800 + p * 18 + (o - 36)] = s;
    }
}

// ---------------- 2b: softmax fg scores ----------------
__global__ void fg_kernel(const float* __restrict__ out) {
    int t = blockIdx.x * 256 + threadIdx.x;
    if (t >= NIMG * NANCH) return;
    int n = t / NANCH, i = t % NANCH;
    int p = i / 9, a = i % 9;
    const float* s = out + OFF_SCORES + (size_t)n * 55800 + p * 18 + a * 2;
    float s0 = s[0], s1 = s[1];
    float m = fmaxf(s0, s1);
    float e0 = expf(s0 - m);
    float e1 = expf(s1 - m);
    g_fg[t] = e1 / (e0 + e1);
}

// ---------------- 3: anchors ----------------
__global__ void anchor_kernel(float* __restrict__ out) {
    int t = blockIdx.x * 256 + threadIdx.x;
    if (t >= NANCH) return;
    int p = t / 9, a = t % 9;
    int y = p / WW, x = p - y * WW;
    int ridx = a / 3, sidx = a % 3;
    double r = (ridx == 0) ? 0.5 : ((ridx == 1) ? 1.0 : 2.0);
    double s = (sidx == 0) ? 8.0 : ((sidx == 1) ? 16.0 : 32.0);
    double hb = 16.0 * s * sqrt(r);
    double wb = 16.0 * s * sqrt(1.0 / r);
    float a0 = (float)(8.0 - hb / 2.0);
    float a1 = (float)(8.0 - wb / 2.0);
    float a2 = (float)(8.0 + hb / 2.0);
    float a3 = (float)(8.0 + wb / 2.0);
    float sy = (float)y * 16.0f, sx = (float)x * 16.0f;
    float v0 = a0 + sy, v1 = a1 + sx;
    float v2 = a2 + sy, v3 = a3 + sx;
    g_anchor[t * 4 + 0] = v0; g_anchor[t * 4 + 1] = v1;
    g_anchor[t * 4 + 2] = v2; g_anchor[t * 4 + 3] = v3;
    out[OFF_ANCH + t * 4 + 0] = v0; out[OFF_ANCH + t * 4 + 1] = v1;
    out[OFF_ANCH + t * 4 + 2] = v2; out[OFF_ANCH + t * 4 + 3] = v3;
}

// ---------------- 4: decode boxes + clip + filter + pack sort keys ----------------
// Packs (score-key, inverse-index) into one u64: descending u64 order is
// exactly (key desc, index asc) == the previous comparator.
__global__ void decode_kernel(const float* __restrict__ out, const void* ph, const void* pw) {
    int t = blockIdx.x * 256 + threadIdx.x;
    if (t >= NIMG * NPAD) return;
    int n = t >> 15, i = t & (NPAD - 1);
    if (i >= NANCH) {
        g_skey[t] = (unsigned long long)(unsigned)(NPAD - 1 - i);
        return;
    }
    float fh = read_scalar(ph), fw = read_scalar(pw);
    const float* A = &g_anchor[i * 4];
    float ah = A[2] - A[0];
    float aw = A[3] - A[1];
    float cy = A[0] + 0.5f * ah;
    float cx = A[1] + 0.5f * aw;
    const float* L = out + (size_t)n * 111600 + (size_t)i * 4;
    float dy = L[0], dx = L[1], dh = L[2], dw = L[3];
    float ncy = dy * ah + cy;
    float ncx = dx * aw + cx;
    float nh = expf(dh) * ah;
    float nw = expf(dw) * aw;
    float b0 = ncy - 0.5f * nh;
    float b1 = ncx - 0.5f * nw;
    float b2 = ncy + 0.5f * nh;
    float b3 = ncx + 0.5f * nw;
    b0 = fminf(fmaxf(b0, 0.f), fh);
    b1 = fminf(fmaxf(b1, 0.f), fw);
    b2 = fminf(fmaxf(b2, 0.f), fh);
    b3 = fminf(fmaxf(b3, 0.f), fw);
    float hs = b2 - b0;
    float ws = b3 - b1;
    bool keep = (hs >= 16.f) && (ws >= 16.f);
    float sc = keep ? g_fg[n * NANCH + i] : -__int_as_float(0x7F800000);
    ((float4*)g_roi)[n * NANCH + i] = make_float4(b0, b1, b2, b3);
    g_skey[t] = ((unsigned long long)packf(sc) << 16)
              | (unsigned long long)(unsigned)(NPAD - 1 - i);
}

// ---------------- 5: tiled multi-kernel bitonic sort (desc u64) ----------------
// Identical comparison network as before -> identical total order.
#define TILE 2048

// 5a: local full sort of 2048-tiles through k=2..2048
__global__ void __launch_bounds__(1024) sort_local_full() {
    __shared__ unsigned long long sk[TILE];
    int n = blockIdx.x >> 4;
    int T = blockIdx.x & 15;
    int tid = threadIdx.x;
    unsigned long long* base = g_skey + (size_t)n * NPAD + (size_t)T * TILE;
    sk[tid] = base[tid];
    sk[tid + 1024] = base[tid + 1024];
    __syncthreads();
    int gbase = T * TILE;
    for (int k = 2; k <= TILE; k <<= 1) {
        for (int j = k >> 1; j > 0; j >>= 1) {
            int i = ((tid & ~(j - 1)) << 1) | (tid & (j - 1));   // tid -> pair lead
            int ixj = i | j;
            int gi = gbase + i;
            unsigned long long a = sk[i], b = sk[ixj];
            bool doswap = (a < b) ^ ((gi & k) != 0);
            if (doswap) { sk[i] = b; sk[ixj] = a; }
            __syncthreads();
        }
    }
    base[tid] = sk[tid];
    base[tid + 1024] = sk[tid + 1024];
}

// 5b: one global pass (j >= 2048)
__global__ void sort_global_pass(int k, int j) {
    int t = blockIdx.x * 256 + threadIdx.x;       // pair id, NIMG*NPAD/2 pairs
    if (t >= NIMG * NPAD / 2) return;
    int n = t / (NPAD / 2);
    int q = t % (NPAD / 2);
    int i = ((q & ~(j - 1)) << 1) | (q & (j - 1));
    int ixj = i | j;
    unsigned long long* base = g_skey + (size_t)n * NPAD;
    unsigned long long a = base[i], b = base[ixj];
    bool doswap = (a < b) ^ ((i & k) != 0);
    if (doswap) { base[i] = b; base[ixj] = a; }
}

// 5c: local tail passes (j = 1024..1) for a given k
__global__ void __launch_bounds__(1024) sort_local_tail(int k) {
    __shared__ unsigned long long sk[TILE];
    int n = blockIdx.x >> 4;
    int T = blockIdx.x & 15;
    int tid = threadIdx.x;
    unsigned long long* base = g_skey + (size_t)n * NPAD + (size_t)T * TILE;
    sk[tid] = base[tid];
    sk[tid + 1024] = base[tid + 1024];
    __syncthreads();
    int gbase = T * TILE;
    for (int j = 1024; j > 0; j >>= 1) {
        int i = ((tid & ~(j - 1)) << 1) | (tid & (j - 1));
        int ixj = i | j;
        int gi = gbase + i;
        unsigned long long a = sk[i], b = sk[ixj];
        bool doswap = (a < b) ^ ((gi & k) != 0);
        if (doswap) { sk[i] = b; sk[ixj] = a; }
        __syncthreads();
    }
    base[tid] = sk[tid];
    base[tid + 1024] = sk[tid + 1024];
}

// 5d: gather top-NPRE boxes + keys
__global__ void gather_kernel() {
    int t = blockIdx.x * 256 + threadIdx.x;
    if (t >= NIMG * NPRE) return;
    int n = t / NPRE, l = t % NPRE;
    unsigned long long pk = g_skey[(size_t)n * NPAD + l];
    unsigned int key = (unsigned int)(pk >> 16);
    int idx = NPAD - 1 - (int)(pk & 0xFFFFull);
    g_topkey[t] = key;
    ((float4*)g_topbox)[t] = ((const float4*)g_roi)[n * NANCH + idx];
}

// ---------------- 6: literal-reference NMS ----------------
#define NMS_CHUNK 6
__global__ void __launch_bounds__(1024) nms_kernel() {
    __shared__ unsigned int skey[NPRE];
    __shared__ unsigned long long warpred[32];
    int n = blockIdx.x;
    int tid = threadIdx.x;
    int lane = tid & 31;
    int wid = tid >> 5;

    float4 myb[NMS_CHUNK];
#pragma unroll
    for (int k = 0; k < NMS_CHUNK; k++) {
        int l = tid + k * 1024;
        myb[k] = (l < NPRE) ? ((const float4*)g_topbox)[n * NPRE + l]
                            : make_float4(0, 0, 0, 0);
    }
    for (int l = tid; l < NPRE; l += 1024)
        skey[l] = g_topkey[n * NPRE + l];
    __syncthreads();

    for (int it = 0; it < NPOST; ++it) {
        unsigned long long best = 0ull;
#pragma unroll
        for (int k = 0; k < NMS_CHUNK; k++) {
            int l = tid + k * 1024;
            if (l < NPRE) {
                unsigned long long cand =
                    ((unsigned long long)skey[l] << 32) | (unsigned int)(NPRE - l);
                if (cand > best) best = cand;
            }
        }
#pragma unroll
        for (int o = 16; o > 0; o >>= 1) {
            unsigned long long v = __shfl_xor_sync(0xFFFFFFFFu, best, o);
            if (v > best) best = v;
        }
        if (lane == 0) warpred[wid] = best;
        __syncthreads();
        if (tid < 32) {
            unsigned long long v = warpred[tid];
#pragma unroll
            for (int o = 16; o > 0; o >>= 1) {
                unsigned long long u = __shfl_xor_sync(0xFFFFFFFFu, v, o);
                if (u > v) v = u;
            }
            if (tid == 0) warpred[0] = v;
        }
        __syncthreads();
        unsigned long long win = warpred[0];
        unsigned int wkey = (unsigned int)(win >> 32);
        int j = NPRE - (int)(win & 0xFFFFFFFFu);
        bool ok = (wkey > NEGINF_KEY);
        if (tid == 0) {
            g_sel[n * NPOST + it] = ok ? j : 0;
            g_val[n * NPOST + it] = ok ? 1 : 0;
        }
        __syncthreads();
        if (ok) {
            float4 bj = ((const float4*)g_topbox)[n * NPRE + j];
            float aj = (bj.z - bj.x) * (bj.w - bj.y);
#pragma unroll
            for (int k = 0; k < NMS_CHUNK; k++) {
                int l = tid + k * 1024;
                if (l < NPRE) {
                    float4 B = myb[k];
                    float ty = fmaxf(bj.x, B.x), tx = fmaxf(bj.y, B.y);
                    float by = fminf(bj.z, B.z), bx = fminf(bj.w, B.w);
                    float ih = fmaxf(by - ty, 0.f);
                    float iw = fmaxf(bx - tx, 0.f);
                    float inter = __fmul_rn(ih, iw);
                    float hl = B.z - B.x;
                    float wl = B.w - B.y;
                    float den = (fmaf(hl, wl, aj) - inter) + 1e-10f;
                    float iou = inter / den;
                    if (iou > 0.7f) skey[l] = NEGINF_KEY;
                }
            }
        }
        __syncthreads();
    }
}

// ---------------- 7: emit rois + roi_indices ----------------
__global__ void output_kernel(float* __restrict__ out) {
    int t = blockIdx.x * 256 + threadIdx.x;
    if (t >= NIMG * NPOST) return;
    int n = t / NPOST;
    int sel = g_sel[t];
    int val = g_val[t];
    float4 b = val ? ((const float4*)g_topbox)[n * NPRE + sel] : make_float4(0, 0, 0, 0);
    ((float4*)(out + OFF_ROIS))[t] = b;
    out[OFF_RIDX + t] = (float)n;
}

// ---------------- launch ----------------
extern "C" void kernel_launch(void* const* d_in, const int* in_sizes, int n_in,
                              void* d_out, int out_size)
{
    const float* x   = (const float*)d_in[0];
    const float* c1w = (const float*)d_in[1];
    const float* c1b = (const float*)d_in[2];
    const float* sw  = (const float*)d_in[3];
    const float* sb  = (const float*)d_in[4];
    const float* lw  = (const float*)d_in[5];
    const float* lb  = (const float*)d_in[6];
    const void*  ph  = d_in[7];
    const void*  pw  = d_in[8];
    float* out = (float*)d_out;

    wtrans_kernel<<<(CH * CH * 9 + 255) / 256, 256>>>(c1w);
    conv3x3_kernel<<<dim3(HH, 8, NIMG), 256>>>(x, c1b);
    heads_kernel<<<NIMG * 388, 256>>>(lw, lb, sw, sb, out);
    fg_kernel<<<(NIMG * NANCH + 255) / 256, 256>>>(out);
    anchor_kernel<<<(NANCH + 255) / 256, 256>>>(out);
    decode_kernel<<<(NIMG * NPAD) / 256, 256>>>(out, ph, pw);

    // tiled bitonic sort: local tiles on all SMs, global passes for j>=2048
    sort_local_full<<<NIMG * 16, 1024>>>();
    int npairs_blocks = (NIMG * NPAD / 2 + 255) / 256;
    for (int k = 4096; k <= NPAD; k <<= 1) {
        for (int j = k >> 1; j >= TILE; j >>= 1)
            sort_global_pass<<<npairs_blocks, 256>>>(k, j);
        sort_local_tail<<<NIMG * 16, 1024>>>(k);
    }
    gather_kernel<<<(NIMG * NPRE + 255) / 256, 256>>>();

    nms_kernel<<<NIMG, 1024>>>();
    output_kernel<<<(NIMG * NPOST + 255) / 256, 256>>>(out);
}

// round 14
// speedup vs baseline: 1.6809x; 1.0303x over previous
#include <cuda_runtime.h>
#include <cuda_bf16.h>
#include <math.h>

#define NIMG 8
#define CH 512
#define HH 50
#define WW 62
#define HW 3100            // 50*62
#define NANCH 27900        // HW*9
#define NPAD 32768
#define NPRE 6000
#define NPOST 300
#define NWORDS 188         // ceil(6000/32)

#define OFF_SCORES 892800
#define OFF_ROIS   1339200
#define OFF_RIDX   1348800
#define OFF_ANCH   1351200

// ---------------- scratch (device globals; no allocation) ----------------
__device__ float              g_hpart[(size_t)8 * NIMG * HW * CH];  // per-chunk partials (406MB)
__device__ float              g_h[NIMG * HW * CH];
__device__ float              g_wt[9 * CH * CH];
__device__ float              g_fg[NIMG * NANCH];
__device__ float              g_roi[NIMG * NANCH * 4];
__device__ float              g_anchor[NANCH * 4];
__device__ unsigned long long g_skey[NIMG * NPAD];   // packed (key<<16)|(NPAD-1-idx)
__device__ float              g_topbox[NIMG * NPRE * 4];
__device__ unsigned int       g_topkey[NIMG * NPRE];
__device__ int                g_sel[NIMG * NPOST];
__device__ int                g_val[NIMG * NPOST];

__device__ __forceinline__ unsigned int packf(float f) {
    unsigned int u = __float_as_uint(f);
    return (u & 0x80000000u) ? ~u : (u | 0x80000000u);
}
#define NEGINF_KEY 0x007FFFFFu   // packf(-inf)

__device__ __forceinline__ float read_scalar(const void* p) {
    int iv = *(const int*)p;
    float fv = *(const float*)p;
    if (iv > 0 && iv < 100000) return (float)iv;
    return fv;
}

// ---------------- 0: weight transpose ----------------
__global__ void wtrans_kernel(const float* __restrict__ w) {
    int t = blockIdx.x * 256 + threadIdx.x;
    if (t >= CH * CH * 9) return;
    int tap = t % 9;
    int ci  = (t / 9) % CH;
    int oc  = t / (9 * CH);
    g_wt[(tap * CH + ci) * CH + oc] = w[t];
}

// ---------------- 1a: conv chunk kernel ----------------
// One 64-ci chunk per block. FMA chain per output identical to the passing
// kernel: c0 ascending within the chunk, then ci, then tap. Writes raw
// partial sums (no bias/relu) to g_hpart[v].
__global__ void __launch_bounds__(256) conv_chunk_kernel(const float* __restrict__ x)
{
    __shared__ float As[8 * 9 * 64];
    __shared__ float Bp[8 * 4 * 64];

    int tid = threadIdx.x;
    int ty = tid >> 4;
    int tx = tid & 15;
    int y0  = blockIdx.x;
    int ocB = blockIdx.y * 64;
    int z   = blockIdx.z;
    int n   = z >> 3;
    int v   = z & 7;

    float acc[4][4];
#pragma unroll
    for (int i = 0; i < 4; i++)
#pragma unroll
        for (int j = 0; j < 4; j++) acc[i][j] = 0.f;

#pragma unroll 1
    for (int cb = 0; cb < 8; cb++) {
        int c0 = v * 64 + cb * 8;
#pragma unroll
        for (int l = 0; l < 18; l++) {
            int t2 = tid + l * 256;
            int oc  = t2 & 63;
            int rest = t2 >> 6;
            int tap = rest % 9;
            int ci  = rest / 9;
            As[ci * 576 + tap * 64 + oc] =
                g_wt[((size_t)tap * CH + c0 + ci) * CH + ocB + oc];
        }
#pragma unroll
        for (int l = 0; l < 8; l++) {
            int t2 = tid + l * 256;
            int c  = t2 & 63;
            int r  = (t2 >> 6) & 3;
            int ci = t2 >> 8;
            int yy = y0 + r - 1;
            int xx = c - 1;
            float vv = 0.f;
            if (yy >= 0 && yy < HH && xx >= 0 && xx < WW)
                vv = x[(((size_t)n * CH + c0 + ci) * HH + yy) * WW + xx];
            Bp[ci * 256 + r * 64 + c] = vv;
        }
        __syncthreads();

#pragma unroll
        for (int ci = 0; ci < 8; ci++) {
#pragma unroll
            for (int tap = 0; tap < 9; tap++) {
                int dy = tap / 3, dx = tap % 3;
                const float4 a4 = *(const float4*)&As[ci * 576 + tap * 64 + ty * 4];
                const float* brow = &Bp[ci * 256 + dy * 64 + tx * 4 + dx];
                float b0 = brow[0], b1 = brow[1], b2 = brow[2], b3 = brow[3];
                acc[0][0] = fmaf(a4.x, b0, acc[0][0]);
                acc[0][1] = fmaf(a4.x, b1, acc[0][1]);
                acc[0][2] = fmaf(a4.x, b2, acc[0][2]);
                acc[0][3] = fmaf(a4.x, b3, acc[0][3]);
                acc[1][0] = fmaf(a4.y, b0, acc[1][0]);
                acc[1][1] = fmaf(a4.y, b1, acc[1][1]);
                acc[1][2] = fmaf(a4.y, b2, acc[1][2]);
                acc[1][3] = fmaf(a4.y, b3, acc[1][3]);
                acc[2][0] = fmaf(a4.z, b0, acc[2][0]);
                acc[2][1] = fmaf(a4.z, b1, acc[2][1]);
                acc[2][2] = fmaf(a4.z, b2, acc[2][2]);
                acc[2][3] = fmaf(a4.z, b3, acc[2][3]);
                acc[3][0] = fmaf(a4.w, b0, acc[3][0]);
                acc[3][1] = fmaf(a4.w, b1, acc[3][1]);
                acc[3][2] = fmaf(a4.w, b2, acc[3][2]);
                acc[3][3] = fmaf(a4.w, b3, acc[3][3]);
            }
        }
        __syncthreads();
    }

    size_t vbase = (size_t)v * NIMG * HW * CH;
#pragma unroll
    for (int j = 0; j < 4; j++) {
        int px = tx * 4 + j;
        if (px >= WW) continue;
        int p = y0 * WW + px;
#pragma unroll
        for (int i = 0; i < 4; i++) {
            int oc = ocB + ty * 4 + i;
            g_hpart[vbase + ((size_t)n * HW + p) * CH + oc] = acc[i][j];
        }
    }
}

// ---------------- 1b: combine partials (exact pairwise tree) + bias + ReLU ----------------
__global__ void conv_combine_kernel(const float* __restrict__ bias) {
    int t = blockIdx.x * 256 + threadIdx.x;
    const int TOT = NIMG * HW * CH;
    if (t >= TOT) return;
    int oc = t & (CH - 1);
    const size_t S = (size_t)NIMG * HW * CH;
    float a0 = g_hpart[t];
    float a1 = g_hpart[S + t];
    float a2 = g_hpart[2 * S + t];
    float a3 = g_hpart[3 * S + t];
    float a4 = g_hpart[4 * S + t];
    float a5 = g_hpart[5 * S + t];
    float a6 = g_hpart[6 * S + t];
    float a7 = g_hpart[7 * S + t];
    float s01 = __fadd_rn(a0, a1);
    float s23 = __fadd_rn(a2, a3);
    float s45 = __fadd_rn(a4, a5);
    float s67 = __fadd_rn(a6, a7);
    float r = __fadd_rn(__fadd_rn(s01, s23), __fadd_rn(s45, s67));
    float vv = r + bias[oc];
    g_h[t] = fmaxf(vv, 0.f);
}

// ---------------- 2: head 1x1 convs ----------------
__global__ void heads_kernel(const float* __restrict__ loc_w, const float* __restrict__ loc_b,
                             const float* __restrict__ sc_w,  const float* __restrict__ sc_b,
                             float* __restrict__ out)
{
    __shared__ float hs[8 * CH];
    int g = blockIdx.x;
    int n = g / 388;
    int p0 = (g % 388) * 8;
    for (int l = threadIdx.x; l < 8 * CH; l += 256) {
        int pp = l >> 9, c = l & 511;
        int p = p0 + pp;
        hs[l] = (p < HW) ? g_h[((size_t)n * HW + p) * CH + c] : 0.f;
    }
    __syncthreads();
    for (int job = threadIdx.x; job < 432; job += 256) {
        int pp = job / 54, o = job % 54;
        int p = p0 + pp;
        if (p >= HW) continue;
        const float* wrow;
        float b;
        if (o < 36) { wrow = loc_w + o * CH; b = loc_b[o]; }
        else        { wrow = sc_w + (o - 36) * CH; b = sc_b[o - 36]; }
        const float* h = &hs[pp * CH];
        float sv[8];
#pragma unroll
        for (int v = 0; v < 8; v++) {
            float s = 0.f;
            int base = v * 64;
#pragma unroll 8
            for (int c = 0; c < 64; c++)
                s = fmaf(h[base + c], wrow[base + c], s);
            sv[v] = s;
        }
        float s01 = __fadd_rn(sv[0], sv[1]);
        float s23 = __fadd_rn(sv[2], sv[3]);
        float s45 = __fadd_rn(sv[4], sv[5]);
        float s67 = __fadd_rn(sv[6], sv[7]);
        float s = __fadd_rn(__fadd_rn(s01, s23), __fadd_rn(s45, s67)) + b;
        if (o < 36) out[(size_t)n * 111600 + p * 36 + o] = s;
        else        out[OFF_SCORES + (size_t)n * 55800 + p * 18 + (o - 36)] = s;
    }
}

// ---------------- 2b: softmax fg scores ----------------
__global__ void fg_kernel(const float* __restrict__ out) {
    int t = blockIdx.x * 256 + threadIdx.x;
    if (t >= NIMG * NANCH) return;
    int n = t / NANCH, i = t % NANCH;
    int p = i / 9, a = i % 9;
    const float* s = out + OFF_SCORES + (size_t)n * 55800 + p * 18 + a * 2;
    float s0 = s[0], s1 = s[1];
    float m = fmaxf(s0, s1);
    float e0 = expf(s0 - m);
    float e1 = expf(s1 - m);
    g_fg[t] = e1 / (e0 + e1);
}

// ---------------- 3: anchors ----------------
__global__ void anchor_kernel(float* __restrict__ out) {
    int t = blockIdx.x * 256 + threadIdx.x;
    if (t >= NANCH) return;
    int p = t / 9, a = t % 9;
    int y = p / WW, x = p - y * WW;
    int ridx = a / 3, sidx = a % 3;
    double r = (ridx == 0) ? 0.5 : ((ridx == 1) ? 1.0 : 2.0);
    double s = (sidx == 0) ? 8.0 : ((sidx == 1) ? 16.0 : 32.0);
    double hb = 16.0 * s * sqrt(r);
    double wb = 16.0 * s * sqrt(1.0 / r);
    float a0 = (float)(8.0 - hb / 2.0);
    float a1 = (float)(8.0 - wb / 2.0);
    float a2 = (float)(8.0 + hb / 2.0);
    float a3 = (float)(8.0 + wb / 2.0);
    float sy = (float)y * 16.0f, sx = (float)x * 16.0f;
    float v0 = a0 + sy, v1 = a1 + sx;
    float v2 = a2 + sy, v3 = a3 + sx;
    g_anchor[t * 4 + 0] = v0; g_anchor[t * 4 + 1] = v1;
    g_anchor[t * 4 + 2] = v2; g_anchor[t * 4 + 3] = v3;
    out[OFF_ANCH + t * 4 + 0] = v0; out[OFF_ANCH + t * 4 + 1] = v1;
    out[OFF_ANCH + t * 4 + 2] = v2; out[OFF_ANCH + t * 4 + 3] = v3;
}

// ---------------- 4: decode boxes + clip + filter + pack sort keys ----------------
__global__ void decode_kernel(const float* __restrict__ out, const void* ph, const void* pw) {
    int t = blockIdx.x * 256 + threadIdx.x;
    if (t >= NIMG * NPAD) return;
    int n = t >> 15, i = t & (NPAD - 1);
    if (i >= NANCH) {
        g_skey[t] = (unsigned long long)(unsigned)(NPAD - 1 - i);
        return;
    }
    float fh = read_scalar(ph), fw = read_scalar(pw);
    const float* A = &g_anchor[i * 4];
    float ah = A[2] - A[0];
    float aw = A[3] - A[1];
    float cy = A[0] + 0.5f * ah;
    float cx = A[1] + 0.5f * aw;
    const float* L = out + (size_t)n * 111600 + (size_t)i * 4;
    float dy = L[0], dx = L[1], dh = L[2], dw = L[3];
    float ncy = dy * ah + cy;
    float ncx = dx * aw + cx;
    float nh = expf(dh) * ah;
    float nw = expf(dw) * aw;
    float b0 = ncy - 0.5f * nh;
    float b1 = ncx - 0.5f * nw;
    float b2 = ncy + 0.5f * nh;
    float b3 = ncx + 0.5f * nw;
    b0 = fminf(fmaxf(b0, 0.f), fh);
    b1 = fminf(fmaxf(b1, 0.f), fw);
    b2 = fminf(fmaxf(b2, 0.f), fh);
    b3 = fminf(fmaxf(b3, 0.f), fw);
    float hs = b2 - b0;
    float ws = b3 - b1;
    bool keep = (hs >= 16.f) && (ws >= 16.f);
    float sc = keep ? g_fg[n * NANCH + i] : -__int_as_float(0x7F800000);
    ((float4*)g_roi)[n * NANCH + i] = make_float4(b0, b1, b2, b3);
    g_skey[t] = ((unsigned long long)packf(sc) << 16)
              | (unsigned long long)(unsigned)(NPAD - 1 - i);
}

// ---------------- 5: tiled multi-kernel bitonic sort (desc u64) ----------------
#define TILE 2048

__global__ void __launch_bounds__(1024) sort_local_full() {
    __shared__ unsigned long long sk[TILE];
    int n = blockIdx.x >> 4;
    int T = blockIdx.x & 15;
    int tid = threadIdx.x;
    unsigned long long* base = g_skey + (size_t)n * NPAD + (size_t)T * TILE;
    sk[tid] = base[tid];
    sk[tid + 1024] = base[tid + 1024];
    __syncthreads();
    int gbase = T * TILE;
    for (int k = 2; k <= TILE; k <<= 1) {
        for (int j = k >> 1; j > 0; j >>= 1) {
            int i = ((tid & ~(j - 1)) << 1) | (tid & (j - 1));
            int ixj = i | j;
            int gi = gbase + i;
            unsigned long long a = sk[i], b = sk[ixj];
            bool doswap = (a < b) ^ ((gi & k) != 0);
            if (doswap) { sk[i] = b; sk[ixj] = a; }
            __syncthreads();
        }
    }
    base[tid] = sk[tid];
    base[tid + 1024] = sk[tid + 1024];
}

__global__ void sort_global_pass(int k, int j) {
    int t = blockIdx.x * 256 + threadIdx.x;
    if (t >= NIMG * NPAD / 2) return;
    int n = t / (NPAD / 2);
    int q = t % (NPAD / 2);
    int i = ((q & ~(j - 1)) << 1) | (q & (j - 1));
    int ixj = i | j;
    unsigned long long* base = g_skey + (size_t)n * NPAD;
    unsigned long long a = base[i], b = base[ixj];
    bool doswap = (a < b) ^ ((i & k) != 0);
    if (doswap) { base[i] = b; base[ixj] = a; }
}

__global__ void __launch_bounds__(1024) sort_local_tail(int k) {
    __shared__ unsigned long long sk[TILE];
    int n = blockIdx.x >> 4;
    int T = blockIdx.x & 15;
    int tid = threadIdx.x;
    unsigned long long* base = g_skey + (size_t)n * NPAD + (size_t)T * TILE;
    sk[tid] = base[tid];
    sk[tid + 1024] = base[tid + 1024];
    __syncthreads();
    int gbase = T * TILE;
    for (int j = 1024; j > 0; j >>= 1) {
        int i = ((tid & ~(j - 1)) << 1) | (tid & (j - 1));
        int ixj = i | j;
        int gi = gbase + i;
        unsigned long long a = sk[i], b = sk[ixj];
        bool doswap = (a < b) ^ ((gi & k) != 0);
        if (doswap) { sk[i] = b; sk[ixj] = a; }
        __syncthreads();
    }
    base[tid] = sk[tid];
    base[tid + 1024] = sk[tid + 1024];
}

__global__ void gather_kernel() {
    int t = blockIdx.x * 256 + threadIdx.x;
    if (t >= NIMG * NPRE) return;
    int n = t / NPRE, l = t % NPRE;
    unsigned long long pk = g_skey[(size_t)n * NPAD + l];
    unsigned int key = (unsigned int)(pk >> 16);
    int idx = NPAD - 1 - (int)(pk & 0xFFFFull);
    g_topkey[t] = key;
    ((float4*)g_topbox)[t] = ((const float4*)g_roi)[n * NANCH + idx];
}

// ---------------- 6: NMS, first-alive scan ----------------
// Keys are sorted (key desc, idx asc), so the reference argmax over remaining
// scores == the FIRST alive sorted position. Maintain a 188-word alive mask;
// the first-alive position is non-decreasing, so thread 0 scans with a hint.
// IoU formula byte-identical to the passing kernel. Degenerate self-iou<0.7
// repeated-selection behavior preserved (bit stays alive -> same pick again).
#define NMS_CHUNK 6
__global__ void __launch_bounds__(1024) nms_kernel() {
    __shared__ unsigned int alive[NWORDS];
    __shared__ int s_first;
    int n = blockIdx.x;
    int tid = threadIdx.x;

    float4 myb[NMS_CHUNK];
#pragma unroll
    for (int k = 0; k < NMS_CHUNK; k++) {
        int l = tid + k * 1024;
        myb[k] = (l < NPRE) ? ((const float4*)g_topbox)[n * NPRE + l]
                            : make_float4(0, 0, 0, 0);
    }
    if (tid < NWORDS) {
        unsigned int m = 0;
        for (int b = 0; b < 32; b++) {
            int j = tid * 32 + b;
            if (j < NPRE && g_topkey[n * NPRE + j] > NEGINF_KEY) m |= (1u << b);
        }
        alive[tid] = m;
    }
    __syncthreads();

    int hintw = 0;   // meaningful in thread 0 only
    for (int it = 0; it < NPOST; ++it) {
        if (tid == 0) {
            int w = hintw;
            while (w < NWORDS && alive[w] == 0u) w++;
            hintw = w;
            if (w < NWORDS) {
                int f = w * 32 + __ffs(alive[w]) - 1;
                s_first = f;
                g_sel[n * NPOST + it] = f;
                g_val[n * NPOST + it] = 1;
            } else {
                s_first = -1;
                g_sel[n * NPOST + it] = 0;
                g_val[n * NPOST + it] = 0;
            }
        }
        __syncthreads();
        int first = s_first;
        if (first >= 0) {
            float4 bj = ((const float4*)g_topbox)[n * NPRE + first];
            float aj = (bj.z - bj.x) * (bj.w - bj.y);
#pragma unroll
            for (int k = 0; k < NMS_CHUNK; k++) {
                int l = tid + k * 1024;
                if (l < NPRE) {
                    float4 B = myb[k];
                    float ty = fmaxf(bj.x, B.x), tx = fmaxf(bj.y, B.y);
                    float by = fminf(bj.z, B.z), bx = fminf(bj.w, B.w);
                    float ih = fmaxf(by - ty, 0.f);
                    float iw = fmaxf(bx - tx, 0.f);
                    float inter = __fmul_rn(ih, iw);
                    float hl = B.z - B.x;
                    float wl = B.w - B.y;
                    float den = (fmaf(hl, wl, aj) - inter) + 1e-10f;
                    float iou = inter / den;
                    if (iou > 0.7f)
                        atomicAnd(&alive[l >> 5], ~(1u << (l & 31)));
                }
            }
        }
        __syncthreads();
    }
}

// ---------------- 7: emit rois + roi_indices ----------------
__global__ void output_kernel(float* __restrict__ out) {
    int t = blockIdx.x * 256 + threadIdx.x;
    if (t >= NIMG * NPOST) return;
    int n = t / NPOST;
    int sel = g_sel[t];
    int val = g_val[t];
    float4 b = val ? ((const float4*)g_topbox)[n * NPRE + sel] : make_float4(0, 0, 0, 0);
    ((float4*)(out + OFF_ROIS))[t] = b;
    out[OFF_RIDX + t] = (float)n;
}

// ---------------- launch ----------------
extern "C" void kernel_launch(void* const* d_in, const int* in_sizes, int n_in,
                              void* d_out, int out_size)
{
    const float* x   = (const float*)d_in[0];
    const float* c1w = (const float*)d_in[1];
    const float* c1b = (const float*)d_in[2];
    const float* sw  = (const float*)d_in[3];
    const float* sb  = (const float*)d_in[4];
    const float* lw  = (const float*)d_in[5];
    const float* lb  = (const float*)d_in[6];
    const void*  ph  = d_in[7];
    const void*  pw  = d_in[8];
    float* out = (float*)d_out;

    wtrans_kernel<<<(CH * CH * 9 + 255) / 256, 256>>>(c1w);
    conv_chunk_kernel<<<dim3(HH, 8, NIMG * 8), 256>>>(x);
    conv_combine_kernel<<<(NIMG * HW * CH + 255) / 256, 256>>>(c1b);
    heads_kernel<<<NIMG * 388, 256>>>(lw, lb, sw, sb, out);
    fg_kernel<<<(NIMG * NANCH + 255) / 256, 256>>>(out);
    anchor_kernel<<<(NANCH + 255) / 256, 256>>>(out);
    decode_kernel<<<(NIMG * NPAD) / 256, 256>>>(out, ph, pw);

    sort_local_full<<<NIMG * 16, 1024>>>();
    int npairs_blocks = (NIMG * NPAD / 2 + 255) / 256;
    for (int k = 4096; k <= NPAD; k <<= 1) {
        for (int j = k >> 1; j >= TILE; j >>= 1)
            sort_global_pass<<<npairs_blocks, 256>>>(k, j);
        sort_local_tail<<<NIMG * 16, 1024>>>(k);
    }
    gather_kernel<<<(NIMG * NPRE + 255) / 256, 256>>>();

    nms_kernel<<<NIMG, 1024>>>();
    output_kernel<<<(NIMG * NPOST + 255) / 256, 256>>>(out);
}